// round 2
// baseline (speedup 1.0000x reference)
#include <cuda_runtime.h>
#include <cstdint>
#include <cstddef>

#define B_  2048
#define S_  65
#define SW  64
#define D_  256
#define H_  8
#define L_  256
#define HL  2048
#define SD  (S_*D_)   // 16640

// Scratch (device globals: no allocation allowed)
__device__ __align__(16) float g_A[(B_ + SW) * HL];   // preK: rows 0..2047 = origin@Wk, rows 2048..2111 = P@Wk
__device__ __align__(16) float g_res[B_ * HL];        // attention result per (b, h*L + l)

// ---------------- helpers ----------------
__device__ __forceinline__ float sigf(float x) {
    return __fdividef(1.0f, 1.0f + __expf(-x));
}
__device__ __forceinline__ unsigned long long pack2(float x, float y) {
    unsigned long long r;
    asm("mov.b64 %0, {%1, %2};" : "=l"(r) : "f"(x), "f"(y));
    return r;
}
__device__ __forceinline__ void unpack2(unsigned long long v, float& x, float& y) {
    asm("mov.b64 {%0, %1}, %2;" : "=f"(x), "=f"(y) : "l"(v));
}
__device__ __forceinline__ unsigned long long fma2(unsigned long long a, unsigned long long b,
                                                   unsigned long long c) {
    unsigned long long d;
    asm("fma.rn.f32x2 %0, %1, %2, %3;" : "=l"(d) : "l"(a), "l"(b), "l"(c));
    return d;
}
__device__ __forceinline__ void cp16(void* s, const void* g) {
    unsigned sa = (unsigned)__cvta_generic_to_shared(s);
    asm volatile("cp.async.cg.shared.global [%0], [%1], 16;\n" ::"r"(sa), "l"(g));
}
__device__ __forceinline__ void cp_commit() { asm volatile("cp.async.commit_group;\n"); }
template <int N>
__device__ __forceinline__ void cp_wait() { asm volatile("cp.async.wait_group %0;\n" ::"n"(N)); }

// ---------------- 64x256 GEMM core (K in chunks of 16, double buffered) ----------------
// Thread t: tx = t&15 -> cols {tx*4 + g*64 + e : g<4, e<4}; ty = t>>4 -> rows {ty*4+i : i<4}.
// acc2[i][g*2+hf] holds the f32x2 pair for cols (tx*4 + g*64 + hf*2, +1).
template <int NCH>
__device__ __forceinline__ void gemm64x256(const float* __restrict__ rowBase, int rowStride,
                                           const float* __restrict__ Wg,
                                           unsigned long long (&acc2)[4][8],
                                           float (&sA)[2][SW * 16], float (&sB)[2][16 * L_],
                                           int t, int tx, int ty) {
    const int ar = t >> 2;          // A row (0..63)
    const int ac = (t & 3) * 4;     // A col within chunk
    const int br = t >> 4;          // B row (0..15)
    const int bc = (t & 15) * 16;   // B col base

    // chunk loads
    {
        cp16(&sA[0][ar * 16 + ac], rowBase + (size_t)ar * rowStride + ac);
        const float* src = Wg + (size_t)br * L_ + bc;
        float* dst = &sB[0][br * L_ + bc];
        cp16(dst + 0, src + 0); cp16(dst + 4, src + 4);
        cp16(dst + 8, src + 8); cp16(dst + 12, src + 12);
        cp_commit();
    }
#pragma unroll 1
    for (int c = 0; c < NCH; ++c) {
        const int cur = c & 1;
        if (c + 1 < NCH) {
            const int nb = cur ^ 1;
            cp16(&sA[nb][ar * 16 + ac], rowBase + (size_t)ar * rowStride + (c + 1) * 16 + ac);
            const float* src = Wg + (size_t)((c + 1) * 16 + br) * L_ + bc;
            float* dst = &sB[nb][br * L_ + bc];
            cp16(dst + 0, src + 0); cp16(dst + 4, src + 4);
            cp16(dst + 8, src + 8); cp16(dst + 12, src + 12);
            cp_commit();
            cp_wait<1>();
        } else {
            cp_wait<0>();
        }
        __syncthreads();
#pragma unroll
        for (int k4 = 0; k4 < 4; ++k4) {
            float avv[4][4];
#pragma unroll
            for (int i = 0; i < 4; ++i) {
                float4 tmp = *(const float4*)&sA[cur][(ty * 4 + i) * 16 + k4 * 4];
                avv[i][0] = tmp.x; avv[i][1] = tmp.y; avv[i][2] = tmp.z; avv[i][3] = tmp.w;
            }
#pragma unroll
            for (int q = 0; q < 4; ++q) {
                unsigned long long a2[4];
#pragma unroll
                for (int i = 0; i < 4; ++i) a2[i] = pack2(avv[i][q], avv[i][q]);
                const int kk = k4 * 4 + q;
#pragma unroll
                for (int g = 0; g < 4; ++g) {
                    ulonglong2 bb = *(const ulonglong2*)&sB[cur][kk * L_ + tx * 4 + g * 64];
#pragma unroll
                    for (int i = 0; i < 4; ++i) {
                        acc2[i][g * 2 + 0] = fma2(a2[i], bb.x, acc2[i][g * 2 + 0]);
                        acc2[i][g * 2 + 1] = fma2(a2[i], bb.y, acc2[i][g * 2 + 1]);
                    }
                }
            }
        }
        __syncthreads();
    }
}

// ---------------- k1: preK = [origin ; P] @ Wk (raw preactivation) ----------------
__global__ void __launch_bounds__(256, 2)
k1_preK(const float* __restrict__ x, const float* __restrict__ Wk, const float* __restrict__ P) {
    __shared__ __align__(16) float sA[2][SW * 16];
    __shared__ __align__(16) float sB[2][16 * L_];
    const int h = blockIdx.x, mt = blockIdx.y;  // mt: 0..32 (32 origin tiles + 1 P tile)
    const int t = threadIdx.x, tx = t & 15, ty = t >> 4;

    const float* base;
    int stride;
    if (mt < 32) { base = x + (size_t)mt * 64 * SD; stride = SD; }  // origin rows: x[b,0,:]
    else         { base = P; stride = D_; }

    unsigned long long acc2[4][8];
#pragma unroll
    for (int i = 0; i < 4; ++i)
#pragma unroll
        for (int p = 0; p < 8; ++p) acc2[i][p] = 0ull;

    gemm64x256<16>(base, stride, Wk + h * (D_ * L_), acc2, sA, sB, t, tx, ty);

#pragma unroll
    for (int i = 0; i < 4; ++i) {
        const size_t row = (size_t)mt * 64 + ty * 4 + i;
        float* dst = g_A + row * HL + h * L_ + tx * 4;
#pragma unroll
        for (int g = 0; g < 4; ++g)
#pragma unroll
            for (int hf = 0; hf < 2; ++hf) {
                float f0, f1;
                unpack2(acc2[i][g * 2 + hf], f0, f1);
                dst[g * 64 + hf * 2 + 0] = f0;
                dst[g * 64 + hf * 2 + 1] = f1;
            }
    }
}

// ---------------- k2: fused q/k/score/softmax/v/res, one block per (h, b) ----------------
__global__ void __launch_bounds__(256, 2)
k2_main(const float* __restrict__ x, const float* __restrict__ Wq,
        const float* __restrict__ Wv, const float* __restrict__ Wsc) {
    __shared__ __align__(16) float sA[2][SW * 16];
    __shared__ __align__(16) float sB[2][16 * L_];
    __shared__ float sSc[SW];
    __shared__ float sWgt[SW + 1];
    const int h = blockIdx.x, b = blockIdx.y;
    const int t = threadIdx.x, tx = t & 15, ty = t >> 4;
    const float* walk = x + (size_t)b * SD + D_;  // x[b, 1:, :]

    unsigned long long acc2[4][8];
#pragma unroll
    for (int i = 0; i < 4; ++i)
#pragma unroll
        for (int p = 0; p < 8; ++p) acc2[i][p] = 0ull;

    // ---- q preactivation GEMM ----
    gemm64x256<16>(walk, D_, Wq + h * (D_ * L_), acc2, sA, sB, t, tx, ty);

    // ---- q epilogue: score partials (scorePart aliases sB[0], GEMM is done+synced) ----
    float* scorePart = &sB[0][0];  // [64][16]
    {
        const float* pA = g_A + (size_t)b * HL + h * L_ + tx * 4;
        const float* pW = Wsc + h * L_ + tx * 4;
        float ka[16], wv[16];
#pragma unroll
        for (int g = 0; g < 4; ++g) {
            float4 kk4 = *(const float4*)(pA + g * 64);
            float4 ww4 = *(const float4*)(pW + g * 64);
            ka[g * 4 + 0] = kk4.x; ka[g * 4 + 1] = kk4.y; ka[g * 4 + 2] = kk4.z; ka[g * 4 + 3] = kk4.w;
            wv[g * 4 + 0] = ww4.x; wv[g * 4 + 1] = ww4.y; wv[g * 4 + 2] = ww4.z; wv[g * 4 + 3] = ww4.w;
        }
#pragma unroll
        for (int i = 0; i < 4; ++i) {
            const int s = ty * 4 + i;
            const float* pPK = g_A + (size_t)(B_ + s) * HL + h * L_ + tx * 4;
            float ps = 0.f;
#pragma unroll
            for (int g = 0; g < 4; ++g) {
                float4 pk4 = *(const float4*)(pPK + g * 64);
                float pkv[4] = {pk4.x, pk4.y, pk4.z, pk4.w};
#pragma unroll
                for (int hf = 0; hf < 2; ++hf) {
                    float f0, f1;
                    unpack2(acc2[i][g * 2 + hf], f0, f1);
                    const int c0 = g * 4 + hf * 2;
                    const float qa = sigf(f0);
                    const float qb = sigf(f1);
                    const float k0 = sigf(ka[c0 + 0] + pkv[hf * 2 + 0]);
                    const float k1 = sigf(ka[c0 + 1] + pkv[hf * 2 + 1]);
                    ps += __cosf(qa * k0) * wv[c0] + __cosf(qb * k1) * wv[c0 + 1];
                }
            }
            scorePart[s * 16 + tx] = ps;
        }
    }
    __syncthreads();
    if (t < SW) {
        float sc = 0.f;
#pragma unroll
        for (int j = 0; j < 16; ++j) sc += scorePart[t * 16 + j];
        sSc[t] = sc;
    }
    __syncthreads();
    if (t < 32) {
        float v0 = sSc[t], v1 = sSc[t + 32];
        float m = fmaxf(v0, v1);
#pragma unroll
        for (int o = 16; o > 0; o >>= 1) m = fmaxf(m, __shfl_xor_sync(0xffffffffu, m, o));
        float e0 = __expf(v0 - m), e1 = __expf(v1 - m);
        float sm = e0 + e1;
#pragma unroll
        for (int o = 16; o > 0; o >>= 1) sm += __shfl_xor_sync(0xffffffffu, sm, o);
        sWgt[t] = e0;
        sWgt[t + 32] = e1;
        if (t == 0) sWgt[SW] = __fdividef(1.f, sm);
    }
    __syncthreads();

    // ---- v preactivation GEMM ----
#pragma unroll
    for (int i = 0; i < 4; ++i)
#pragma unroll
        for (int p = 0; p < 8; ++p) acc2[i][p] = 0ull;
    gemm64x256<16>(walk, D_, Wv + h * (D_ * L_), acc2, sA, sB, t, tx, ty);

    // ---- v epilogue: weighted partial sums (resPart aliases sB[0]) ----
    float* resPart = &sB[0][0];  // [16][256]
    {
        float r[16];
#pragma unroll
        for (int c = 0; c < 16; ++c) r[c] = 0.f;
#pragma unroll
        for (int i = 0; i < 4; ++i) {
            const float wi = sWgt[ty * 4 + i];
#pragma unroll
            for (int g = 0; g < 4; ++g)
#pragma unroll
                for (int hf = 0; hf < 2; ++hf) {
                    float f0, f1;
                    unpack2(acc2[i][g * 2 + hf], f0, f1);
                    r[g * 4 + hf * 2 + 0] += wi * sigf(f0);
                    r[g * 4 + hf * 2 + 1] += wi * sigf(f1);
                }
        }
#pragma unroll
        for (int g = 0; g < 4; ++g)
#pragma unroll
            for (int c = 0; c < 4; ++c)
                resPart[ty * L_ + tx * 4 + g * 64 + c] = r[g * 4 + c];
    }
    __syncthreads();
    {
        float acc = 0.f;
#pragma unroll
        for (int j = 0; j < 16; ++j) acc += resPart[j * L_ + t];
        g_res[(size_t)b * HL + h * L_ + t] = acc * sWgt[SW];
    }
}

// ---------------- k3: out[:, :256] = sigmoid(res @ O) ----------------
__global__ void __launch_bounds__(256, 2)
k3_out(const float* __restrict__ O, float* __restrict__ out) {
    __shared__ __align__(16) float sA[2][SW * 16];
    __shared__ __align__(16) float sB[2][16 * 64];
    const int ct = blockIdx.x;  // 0..3  (d-tile of 64)
    const int bt = blockIdx.y;  // 0..31 (b-tile of 64)
    const int t = threadIdx.x, tx = t & 15, ty = t >> 4;
    const int ar = t >> 2, ac = (t & 3) * 4;
    const int br = t >> 4, bc = (t & 15) * 4;

    const float* rowBase = g_res + (size_t)bt * 64 * HL;

    unsigned long long acc2[4][2];
#pragma unroll
    for (int i = 0; i < 4; ++i) { acc2[i][0] = 0ull; acc2[i][1] = 0ull; }

    cp16(&sA[0][ar * 16 + ac], rowBase + (size_t)ar * HL + ac);
    cp16(&sB[0][br * 64 + bc], O + (size_t)br * D_ + ct * 64 + bc);
    cp_commit();
#pragma unroll 1
    for (int c = 0; c < 128; ++c) {
        const int cur = c & 1;
        if (c + 1 < 128) {
            const int nb = cur ^ 1;
            cp16(&sA[nb][ar * 16 + ac], rowBase + (size_t)ar * HL + (c + 1) * 16 + ac);
            cp16(&sB[nb][br * 64 + bc], O + (size_t)((c + 1) * 16 + br) * D_ + ct * 64 + bc);
            cp_commit();
            cp_wait<1>();
        } else {
            cp_wait<0>();
        }
        __syncthreads();
#pragma unroll
        for (int k4 = 0; k4 < 4; ++k4) {
            float avv[4][4];
#pragma unroll
            for (int i = 0; i < 4; ++i) {
                float4 tmp = *(const float4*)&sA[cur][(ty * 4 + i) * 16 + k4 * 4];
                avv[i][0] = tmp.x; avv[i][1] = tmp.y; avv[i][2] = tmp.z; avv[i][3] = tmp.w;
            }
#pragma unroll
            for (int q = 0; q < 4; ++q) {
                const int kk = k4 * 4 + q;
                ulonglong2 bb = *(const ulonglong2*)&sB[cur][kk * 64 + tx * 4];
#pragma unroll
                for (int i = 0; i < 4; ++i) {
                    unsigned long long a2 = pack2(avv[i][q], avv[i][q]);
                    acc2[i][0] = fma2(a2, bb.x, acc2[i][0]);
                    acc2[i][1] = fma2(a2, bb.y, acc2[i][1]);
                }
            }
        }
        __syncthreads();
    }
#pragma unroll
    for (int i = 0; i < 4; ++i) {
        const size_t bb = (size_t)bt * 64 + ty * 4 + i;
#pragma unroll
        for (int hf = 0; hf < 2; ++hf) {
            float f0, f1;
            unpack2(acc2[i][hf], f0, f1);
            const int d = ct * 64 + tx * 4 + hf * 2;
            out[bb * 512 + d + 0] = sigf(f0);
            out[bb * 512 + d + 1] = sigf(f1);
        }
    }
}

// ---------------- k4: out[:, 256:512] = origin ----------------
__global__ void k4_copy(const float* __restrict__ x, float* __restrict__ out) {
    const int idx = blockIdx.x * 256 + threadIdx.x;  // one float4 each
    const int b = idx >> 6;
    const int d4 = (idx & 63) * 4;
    float4 v = *(const float4*)(x + (size_t)b * SD + d4);
    *(float4*)(out + (size_t)b * 512 + 256 + d4) = v;
}

// ---------------- launch ----------------
extern "C" void kernel_launch(void* const* d_in, const int* in_sizes, int n_in,
                              void* d_out, int out_size) {
    const float* x  = (const float*)d_in[0];
    const float* Wq = (const float*)d_in[1];
    const float* Wk = (const float*)d_in[2];
    const float* Wv = (const float*)d_in[3];
    const float* W  = (const float*)d_in[4];
    const float* O  = (const float*)d_in[5];
    const float* P  = (const float*)d_in[6];
    // d_in[7] = bias: provably cancels under softmax (constant shift per (b,h)); unused.
    float* out = (float*)d_out;

    k1_preK<<<dim3(H_, 33), 256>>>(x, Wk, P);
    k2_main<<<dim3(H_, B_), 256>>>(x, Wq, Wv, W);
    k3_out<<<dim3(4, 32), 256>>>(O, out);
    k4_copy<<<512, 256>>>(x, out);
}

// round 3
// speedup vs baseline: 1.0017x; 1.0017x over previous
#include <cuda_runtime.h>
#include <cstdint>
#include <cstddef>

#define B_  2048
#define S_  65
#define SW  64
#define D_  256
#define H_  8
#define L_  256
#define HL  2048
#define SD  (S_*D_)   // 16640

// Scratch (device globals: no allocation allowed)
__device__ __align__(16) float g_A[(B_ + SW) * HL];   // preK: rows 0..2047 = origin@Wk, rows 2048..2111 = P@Wk
__device__ __align__(16) float g_res[B_ * HL];        // attention result per (b, h*L + l)

// ---------------- helpers ----------------
__device__ __forceinline__ float sigf(float x) {
    return __fdividef(1.0f, 1.0f + __expf(-x));
}
__device__ __forceinline__ unsigned long long pack2(float x, float y) {
    unsigned long long r;
    asm("mov.b64 %0, {%1, %2};" : "=l"(r) : "f"(x), "f"(y));
    return r;
}
__device__ __forceinline__ void unpack2(unsigned long long v, float& x, float& y) {
    asm("mov.b64 {%0, %1}, %2;" : "=f"(x), "=f"(y) : "l"(v));
}
__device__ __forceinline__ unsigned long long fma2(unsigned long long a, unsigned long long b,
                                                   unsigned long long c) {
    unsigned long long d;
    asm("fma.rn.f32x2 %0, %1, %2, %3;" : "=l"(d) : "l"(a), "l"(b), "l"(c));
    return d;
}
__device__ __forceinline__ void cp16(void* s, const void* g) {
    unsigned sa = (unsigned)__cvta_generic_to_shared(s);
    asm volatile("cp.async.cg.shared.global [%0], [%1], 16;\n" ::"r"(sa), "l"(g));
}
__device__ __forceinline__ void cp_commit() { asm volatile("cp.async.commit_group;\n"); }
template <int N>
__device__ __forceinline__ void cp_wait() { asm volatile("cp.async.wait_group %0;\n" ::"n"(N)); }

// ---------------- 64x256 GEMM core (K in chunks of 16, double buffered) ----------------
// Thread t: tx = t&15 -> cols {tx*4 + g*64 + e : g<4, e<4}; ty = t>>4 -> rows {ty*4+i : i<4}.
// acc2[i][g*2+hf] holds the f32x2 pair for cols (tx*4 + g*64 + hf*2, +1).
template <int NCH>
__device__ __forceinline__ void gemm64x256(const float* __restrict__ rowBase, int rowStride,
                                           const float* __restrict__ Wg,
                                           unsigned long long (&acc2)[4][8],
                                           float (&sA)[2][SW * 16], float (&sB)[2][16 * L_],
                                           int t, int tx, int ty) {
    const int ar = t >> 2;          // A row (0..63)
    const int ac = (t & 3) * 4;     // A col within chunk
    const int br = t >> 4;          // B row (0..15)
    const int bc = (t & 15) * 16;   // B col base

    // chunk loads
    {
        cp16(&sA[0][ar * 16 + ac], rowBase + (size_t)ar * rowStride + ac);
        const float* src = Wg + (size_t)br * L_ + bc;
        float* dst = &sB[0][br * L_ + bc];
        cp16(dst + 0, src + 0); cp16(dst + 4, src + 4);
        cp16(dst + 8, src + 8); cp16(dst + 12, src + 12);
        cp_commit();
    }
#pragma unroll 1
    for (int c = 0; c < NCH; ++c) {
        const int cur = c & 1;
        if (c + 1 < NCH) {
            const int nb = cur ^ 1;
            cp16(&sA[nb][ar * 16 + ac], rowBase + (size_t)ar * rowStride + (c + 1) * 16 + ac);
            const float* src = Wg + (size_t)((c + 1) * 16 + br) * L_ + bc;
            float* dst = &sB[nb][br * L_ + bc];
            cp16(dst + 0, src + 0); cp16(dst + 4, src + 4);
            cp16(dst + 8, src + 8); cp16(dst + 12, src + 12);
            cp_commit();
            cp_wait<1>();
        } else {
            cp_wait<0>();
        }
        __syncthreads();
#pragma unroll
        for (int k4 = 0; k4 < 4; ++k4) {
            float avv[4][4];
#pragma unroll
            for (int i = 0; i < 4; ++i) {
                float4 tmp = *(const float4*)&sA[cur][(ty * 4 + i) * 16 + k4 * 4];
                avv[i][0] = tmp.x; avv[i][1] = tmp.y; avv[i][2] = tmp.z; avv[i][3] = tmp.w;
            }
#pragma unroll
            for (int q = 0; q < 4; ++q) {
                unsigned long long a2[4];
#pragma unroll
                for (int i = 0; i < 4; ++i) a2[i] = pack2(avv[i][q], avv[i][q]);
                const int kk = k4 * 4 + q;
#pragma unroll
                for (int g = 0; g < 4; ++g) {
                    ulonglong2 bb = *(const ulonglong2*)&sB[cur][kk * L_ + tx * 4 + g * 64];
#pragma unroll
                    for (int i = 0; i < 4; ++i) {
                        acc2[i][g * 2 + 0] = fma2(a2[i], bb.x, acc2[i][g * 2 + 0]);
                        acc2[i][g * 2 + 1] = fma2(a2[i], bb.y, acc2[i][g * 2 + 1]);
                    }
                }
            }
        }
        __syncthreads();
    }
}

// ---------------- k1: preK = [origin ; P] @ Wk (raw preactivation) ----------------
__global__ void __launch_bounds__(256, 2)
k1_preK(const float* __restrict__ x, const float* __restrict__ Wk, const float* __restrict__ P) {
    __shared__ __align__(16) float sA[2][SW * 16];
    __shared__ __align__(16) float sB[2][16 * L_];
    const int h = blockIdx.x, mt = blockIdx.y;  // mt: 0..32 (32 origin tiles + 1 P tile)
    const int t = threadIdx.x, tx = t & 15, ty = t >> 4;

    const float* base;
    int stride;
    if (mt < 32) { base = x + (size_t)mt * 64 * SD; stride = SD; }  // origin rows: x[b,0,:]
    else         { base = P; stride = D_; }

    unsigned long long acc2[4][8];
#pragma unroll
    for (int i = 0; i < 4; ++i)
#pragma unroll
        for (int p = 0; p < 8; ++p) acc2[i][p] = 0ull;

    gemm64x256<16>(base, stride, Wk + h * (D_ * L_), acc2, sA, sB, t, tx, ty);

#pragma unroll
    for (int i = 0; i < 4; ++i) {
        const size_t row = (size_t)mt * 64 + ty * 4 + i;
        float* dst = g_A + row * HL + h * L_ + tx * 4;
#pragma unroll
        for (int g = 0; g < 4; ++g)
#pragma unroll
            for (int hf = 0; hf < 2; ++hf) {
                float f0, f1;
                unpack2(acc2[i][g * 2 + hf], f0, f1);
                dst[g * 64 + hf * 2 + 0] = f0;
                dst[g * 64 + hf * 2 + 1] = f1;
            }
    }
}

// ---------------- k2: fused q/k/score/softmax/v/res, one block per (h, b) ----------------
__global__ void __launch_bounds__(256, 2)
k2_main(const float* __restrict__ x, const float* __restrict__ Wq,
        const float* __restrict__ Wv, const float* __restrict__ Wsc) {
    __shared__ __align__(16) float sA[2][SW * 16];
    __shared__ __align__(16) float sB[2][16 * L_];
    __shared__ float sSc[SW];
    __shared__ float sWgt[SW + 1];
    const int h = blockIdx.x, b = blockIdx.y;
    const int t = threadIdx.x, tx = t & 15, ty = t >> 4;
    const float* walk = x + (size_t)b * SD + D_;  // x[b, 1:, :]

    unsigned long long acc2[4][8];
#pragma unroll
    for (int i = 0; i < 4; ++i)
#pragma unroll
        for (int p = 0; p < 8; ++p) acc2[i][p] = 0ull;

    // ---- q preactivation GEMM ----
    gemm64x256<16>(walk, D_, Wq + h * (D_ * L_), acc2, sA, sB, t, tx, ty);

    // ---- q epilogue: score partials (scorePart aliases sB[0], GEMM is done+synced) ----
    float* scorePart = &sB[0][0];  // [64][16]
    {
        const float* pA = g_A + (size_t)b * HL + h * L_ + tx * 4;
        const float* pW = Wsc + h * L_ + tx * 4;
        float ka[16], wv[16];
#pragma unroll
        for (int g = 0; g < 4; ++g) {
            float4 kk4 = *(const float4*)(pA + g * 64);
            float4 ww4 = *(const float4*)(pW + g * 64);
            ka[g * 4 + 0] = kk4.x; ka[g * 4 + 1] = kk4.y; ka[g * 4 + 2] = kk4.z; ka[g * 4 + 3] = kk4.w;
            wv[g * 4 + 0] = ww4.x; wv[g * 4 + 1] = ww4.y; wv[g * 4 + 2] = ww4.z; wv[g * 4 + 3] = ww4.w;
        }
#pragma unroll
        for (int i = 0; i < 4; ++i) {
            const int s = ty * 4 + i;
            const float* pPK = g_A + (size_t)(B_ + s) * HL + h * L_ + tx * 4;
            float ps = 0.f;
#pragma unroll
            for (int g = 0; g < 4; ++g) {
                float4 pk4 = *(const float4*)(pPK + g * 64);
                float pkv[4] = {pk4.x, pk4.y, pk4.z, pk4.w};
#pragma unroll
                for (int hf = 0; hf < 2; ++hf) {
                    float f0, f1;
                    unpack2(acc2[i][g * 2 + hf], f0, f1);
                    const int c0 = g * 4 + hf * 2;
                    const float qa = sigf(f0);
                    const float qb = sigf(f1);
                    const float k0 = sigf(ka[c0 + 0] + pkv[hf * 2 + 0]);
                    const float k1 = sigf(ka[c0 + 1] + pkv[hf * 2 + 1]);
                    ps += __cosf(qa * k0) * wv[c0] + __cosf(qb * k1) * wv[c0 + 1];
                }
            }
            scorePart[s * 16 + tx] = ps;
        }
    }
    __syncthreads();
    if (t < SW) {
        float sc = 0.f;
#pragma unroll
        for (int j = 0; j < 16; ++j) sc += scorePart[t * 16 + j];
        sSc[t] = sc;
    }
    __syncthreads();
    if (t < 32) {
        float v0 = sSc[t], v1 = sSc[t + 32];
        float m = fmaxf(v0, v1);
#pragma unroll
        for (int o = 16; o > 0; o >>= 1) m = fmaxf(m, __shfl_xor_sync(0xffffffffu, m, o));
        float e0 = __expf(v0 - m), e1 = __expf(v1 - m);
        float sm = e0 + e1;
#pragma unroll
        for (int o = 16; o > 0; o >>= 1) sm += __shfl_xor_sync(0xffffffffu, sm, o);
        sWgt[t] = e0;
        sWgt[t + 32] = e1;
        if (t == 0) sWgt[SW] = __fdividef(1.f, sm);
    }
    __syncthreads();

    // ---- v preactivation GEMM ----
#pragma unroll
    for (int i = 0; i < 4; ++i)
#pragma unroll
        for (int p = 0; p < 8; ++p) acc2[i][p] = 0ull;
    gemm64x256<16>(walk, D_, Wv + h * (D_ * L_), acc2, sA, sB, t, tx, ty);

    // ---- v epilogue: weighted partial sums (resPart aliases sB[0]) ----
    float* resPart = &sB[0][0];  // [16][256]
    {
        float r[16];
#pragma unroll
        for (int c = 0; c < 16; ++c) r[c] = 0.f;
#pragma unroll
        for (int i = 0; i < 4; ++i) {
            const float wi = sWgt[ty * 4 + i];
#pragma unroll
            for (int g = 0; g < 4; ++g)
#pragma unroll
                for (int hf = 0; hf < 2; ++hf) {
                    float f0, f1;
                    unpack2(acc2[i][g * 2 + hf], f0, f1);
                    r[g * 4 + hf * 2 + 0] += wi * sigf(f0);
                    r[g * 4 + hf * 2 + 1] += wi * sigf(f1);
                }
        }
#pragma unroll
        for (int g = 0; g < 4; ++g)
#pragma unroll
            for (int c = 0; c < 4; ++c)
                resPart[ty * L_ + tx * 4 + g * 64 + c] = r[g * 4 + c];
    }
    __syncthreads();
    {
        float acc = 0.f;
#pragma unroll
        for (int j = 0; j < 16; ++j) acc += resPart[j * L_ + t];
        g_res[(size_t)b * HL + h * L_ + t] = acc * sWgt[SW];
    }
}

// ---------------- k3: out[:, :256] = sigmoid(res @ O) ----------------
__global__ void __launch_bounds__(256, 2)
k3_out(const float* __restrict__ O, float* __restrict__ out) {
    __shared__ __align__(16) float sA[2][SW * 16];
    __shared__ __align__(16) float sB[2][16 * 64];
    const int ct = blockIdx.x;  // 0..3  (d-tile of 64)
    const int bt = blockIdx.y;  // 0..31 (b-tile of 64)
    const int t = threadIdx.x, tx = t & 15, ty = t >> 4;
    const int ar = t >> 2, ac = (t & 3) * 4;
    const int br = t >> 4, bc = (t & 15) * 4;

    const float* rowBase = g_res + (size_t)bt * 64 * HL;

    unsigned long long acc2[4][2];
#pragma unroll
    for (int i = 0; i < 4; ++i) { acc2[i][0] = 0ull; acc2[i][1] = 0ull; }

    cp16(&sA[0][ar * 16 + ac], rowBase + (size_t)ar * HL + ac);
    cp16(&sB[0][br * 64 + bc], O + (size_t)br * D_ + ct * 64 + bc);
    cp_commit();
#pragma unroll 1
    for (int c = 0; c < 128; ++c) {
        const int cur = c & 1;
        if (c + 1 < 128) {
            const int nb = cur ^ 1;
            cp16(&sA[nb][ar * 16 + ac], rowBase + (size_t)ar * HL + (c + 1) * 16 + ac);
            cp16(&sB[nb][br * 64 + bc], O + (size_t)((c + 1) * 16 + br) * D_ + ct * 64 + bc);
            cp_commit();
            cp_wait<1>();
        } else {
            cp_wait<0>();
        }
        __syncthreads();
#pragma unroll
        for (int k4 = 0; k4 < 4; ++k4) {
            float avv[4][4];
#pragma unroll
            for (int i = 0; i < 4; ++i) {
                float4 tmp = *(const float4*)&sA[cur][(ty * 4 + i) * 16 + k4 * 4];
                avv[i][0] = tmp.x; avv[i][1] = tmp.y; avv[i][2] = tmp.z; avv[i][3] = tmp.w;
            }
#pragma unroll
            for (int q = 0; q < 4; ++q) {
                const int kk = k4 * 4 + q;
                ulonglong2 bb = *(const ulonglong2*)&sB[cur][kk * 64 + tx * 4];
#pragma unroll
                for (int i = 0; i < 4; ++i) {
                    unsigned long long a2 = pack2(avv[i][q], avv[i][q]);
                    acc2[i][0] = fma2(a2, bb.x, acc2[i][0]);
                    acc2[i][1] = fma2(a2, bb.y, acc2[i][1]);
                }
            }
        }
        __syncthreads();
    }
#pragma unroll
    for (int i = 0; i < 4; ++i) {
        const size_t bb = (size_t)bt * 64 + ty * 4 + i;
#pragma unroll
        for (int hf = 0; hf < 2; ++hf) {
            float f0, f1;
            unpack2(acc2[i][hf], f0, f1);
            const int d = ct * 64 + tx * 4 + hf * 2;
            out[bb * 512 + d + 0] = sigf(f0);
            out[bb * 512 + d + 1] = sigf(f1);
        }
    }
}

// ---------------- k4: out[:, 256:512] = origin ----------------
__global__ void k4_copy(const float* __restrict__ x, float* __restrict__ out) {
    const int idx = blockIdx.x * 256 + threadIdx.x;  // one float4 each
    const int b = idx >> 6;
    const int d4 = (idx & 63) * 4;
    float4 v = *(const float4*)(x + (size_t)b * SD + d4);
    *(float4*)(out + (size_t)b * 512 + 256 + d4) = v;
}

// ---------------- launch ----------------
extern "C" void kernel_launch(void* const* d_in, const int* in_sizes, int n_in,
                              void* d_out, int out_size) {
    const float* x  = (const float*)d_in[0];
    const float* Wq = (const float*)d_in[1];
    const float* Wk = (const float*)d_in[2];
    const float* Wv = (const float*)d_in[3];
    const float* W  = (const float*)d_in[4];
    const float* O  = (const float*)d_in[5];
    const float* P  = (const float*)d_in[6];
    // d_in[7] = bias: provably cancels under softmax (constant shift per (b,h)); unused.
    float* out = (float*)d_out;

    k1_preK<<<dim3(H_, 33), 256>>>(x, Wk, P);
    k2_main<<<dim3(H_, B_), 256>>>(x, Wq, Wv, W);
    k3_out<<<dim3(4, 32), 256>>>(O, out);
    k4_copy<<<512, 256>>>(x, out);
}

// round 9
// speedup vs baseline: 1.2743x; 1.2721x over previous
#include <cuda_runtime.h>
#include <cuda_fp16.h>
#include <cstdint>
#include <cstddef>

#define B_  2048
#define S_  65
#define SW  64
#define D_  256
#define H_  8
#define L_  256
#define HL  2048
#define SD  (S_*D_)        // 16640
#define WROWS (B_*SW)      // 131072

// ---------------- device scratch ----------------
__device__ __align__(16) float  g_A[(B_ + SW) * HL];   // preK raw preacts (origin rows + P rows)
__device__ __align__(16) float  g_kP[HL * SW];         // P-part transposed: [h*L+l][s]
__device__ __align__(16) float  g_res[B_ * HL];        // attention result
__device__ __align__(16) __half g_walk_hi[WROWS * D_];
__device__ __align__(16) __half g_walk_lo[WROWS * D_];
__device__ __align__(16) __half g_wq_hi[H_ * L_ * D_]; // Wq^T split, [h][l][d]
__device__ __align__(16) __half g_wq_lo[H_ * L_ * D_];
__device__ __align__(16) __half g_wv_hi[H_ * L_ * D_];
__device__ __align__(16) __half g_wv_lo[H_ * L_ * D_];

// ---------------- helpers ----------------
__device__ __forceinline__ float sigf(float x) {
    return __fdividef(1.0f, 1.0f + __expf(-x));
}
__device__ __forceinline__ unsigned long long pack2(float x, float y) {
    unsigned long long r;
    asm("mov.b64 %0, {%1, %2};" : "=l"(r) : "f"(x), "f"(y));
    return r;
}
__device__ __forceinline__ void unpack2(unsigned long long v, float& x, float& y) {
    asm("mov.b64 {%0, %1}, %2;" : "=f"(x), "=f"(y) : "l"(v));
}
__device__ __forceinline__ unsigned long long fma2(unsigned long long a, unsigned long long b,
                                                   unsigned long long c) {
    unsigned long long d;
    asm("fma.rn.f32x2 %0, %1, %2, %3;" : "=l"(d) : "l"(a), "l"(b), "l"(c));
    return d;
}
__device__ __forceinline__ void cp16(void* s, const void* g) {
    unsigned sa = (unsigned)__cvta_generic_to_shared(s);
    asm volatile("cp.async.cg.shared.global [%0], [%1], 16;\n" ::"r"(sa), "l"(g));
}
__device__ __forceinline__ void cp_commit() { asm volatile("cp.async.commit_group;\n"); }
template <int N>
__device__ __forceinline__ void cp_wait() { asm volatile("cp.async.wait_group %0;\n" ::"n"(N)); }

// m16n8k16 fp16 -> fp32 mma, D accumulates in place
__device__ __forceinline__ void mma16816(float* c, const uint32_t* a, uint32_t b0, uint32_t b1) {
    asm volatile("mma.sync.aligned.m16n8k16.row.col.f32.f16.f16.f32 "
        "{%0,%1,%2,%3}, {%4,%5,%6,%7}, {%8,%9}, {%0,%1,%2,%3};"
        : "+f"(c[0]), "+f"(c[1]), "+f"(c[2]), "+f"(c[3])
        : "r"(a[0]), "r"(a[1]), "r"(a[2]), "r"(a[3]), "r"(b0), "r"(b1));
}

// ---------------- k2 smem layout (bytes) ----------------
#define KCH   32
#define ASTR  40                        // padded row stride (fp16 elems) -> 80B rows, conflict-free
#define BUF_A (128*ASTR*2)              // 10240
#define BUF_B (256*ASTR*2)              // 20480
#define OFF_AH 0
#define OFF_AL BUF_A
#define OFF_BH (2*BUF_A)
#define OFF_BL (2*BUF_A + BUF_B)
#define BUF_SZ (2*BUF_A + 2*BUF_B)      // 61440
#define KPSTR  68
#define SM_KP  (2*BUF_SZ)               // 122880
#define SM_OK  (SM_KP + 256*KPSTR*4)    // 192512
#define SM_WSC (SM_OK + 2048)           // 194560
#define SM_SP  (SM_WSC + 1024)          // 195584
#define SM_WGT (SM_SP + 1024)           // 196608
#define SM_VP  (SM_WGT + 512)           // 197120
#define SM_INV (SM_VP + 4096)           // 201216
#define SMEM_K2 201280

// ---------------- prep: split walk rows into fp16 hi/lo ----------------
__global__ void p_walk(const float* __restrict__ x) {
    const int idx = blockIdx.x * 256 + threadIdx.x;
    const int row = idx >> 6, c4 = (idx & 63) * 4;
    const int b = row >> 6, s = row & 63;
    float4 v = *(const float4*)(x + (size_t)b * SD + (size_t)(s + 1) * D_ + c4);
    __half h0 = __float2half_rn(v.x), h1 = __float2half_rn(v.y);
    __half h2 = __float2half_rn(v.z), h3 = __float2half_rn(v.w);
    const size_t o = (size_t)row * D_ + c4;
    *(__half2*)(g_walk_hi + o)     = __halves2half2(h0, h1);
    *(__half2*)(g_walk_hi + o + 2) = __halves2half2(h2, h3);
    *(__half2*)(g_walk_lo + o)     = __halves2half2(__float2half_rn(v.x - __half2float(h0)),
                                                    __float2half_rn(v.y - __half2float(h1)));
    *(__half2*)(g_walk_lo + o + 2) = __halves2half2(__float2half_rn(v.z - __half2float(h2)),
                                                    __float2half_rn(v.w - __half2float(h3)));
}

// ---------------- prep: transpose + split weights (h,d,l) -> (h,l,d) ----------------
__global__ void p_wt(const float* __restrict__ Wq, const float* __restrict__ Wv) {
    const int idx = blockIdx.x * 256 + threadIdx.x;
    const int h = idx >> 16, l = (idx >> 8) & 255, d = idx & 255;
    const float* src = (blockIdx.y == 0) ? Wq : Wv;
    float v = src[(size_t)h * 65536 + (size_t)d * 256 + l];
    __half hi = __float2half_rn(v);
    __half lo = __float2half_rn(v - __half2float(hi));
    if (blockIdx.y == 0) { g_wq_hi[idx] = hi; g_wq_lo[idx] = lo; }
    else                 { g_wv_hi[idx] = hi; g_wv_lo[idx] = lo; }
}

// ---------------- k1t: transpose P-part of preK into [hl][s] ----------------
__global__ void k1t(void) {
    const int idx = blockIdx.x * 256 + threadIdx.x;
    const int hl = idx >> 6, s = idx & 63;
    g_kP[idx] = g_A[(size_t)(B_ + s) * HL + hl];
}

// ---------------- fp32 GEMM core (k1, k3) ----------------
template <int NCH>
__device__ __forceinline__ void gemm64x256(const float* __restrict__ rowBase, int rowStride,
                                           const float* __restrict__ Wg,
                                           unsigned long long (&acc2)[4][8],
                                           float (&sA)[2][SW * 16], float (&sB)[2][16 * L_],
                                           int t, int tx, int ty) {
    const int ar = t >> 2, ac = (t & 3) * 4;
    const int br = t >> 4, bc = (t & 15) * 16;
    {
        cp16(&sA[0][ar * 16 + ac], rowBase + (size_t)ar * rowStride + ac);
        const float* src = Wg + (size_t)br * L_ + bc;
        float* dst = &sB[0][br * L_ + bc];
        cp16(dst + 0, src + 0); cp16(dst + 4, src + 4);
        cp16(dst + 8, src + 8); cp16(dst + 12, src + 12);
        cp_commit();
    }
#pragma unroll 1
    for (int c = 0; c < NCH; ++c) {
        const int cur = c & 1;
        if (c + 1 < NCH) {
            const int nb = cur ^ 1;
            cp16(&sA[nb][ar * 16 + ac], rowBase + (size_t)ar * rowStride + (c + 1) * 16 + ac);
            const float* src = Wg + (size_t)((c + 1) * 16 + br) * L_ + bc;
            float* dst = &sB[nb][br * L_ + bc];
            cp16(dst + 0, src + 0); cp16(dst + 4, src + 4);
            cp16(dst + 8, src + 8); cp16(dst + 12, src + 12);
            cp_commit();
            cp_wait<1>();
        } else {
            cp_wait<0>();
        }
        __syncthreads();
#pragma unroll
        for (int k4 = 0; k4 < 4; ++k4) {
            float avv[4][4];
#pragma unroll
            for (int i = 0; i < 4; ++i) {
                float4 tmp = *(const float4*)&sA[cur][(ty * 4 + i) * 16 + k4 * 4];
                avv[i][0] = tmp.x; avv[i][1] = tmp.y; avv[i][2] = tmp.z; avv[i][3] = tmp.w;
            }
#pragma unroll
            for (int q = 0; q < 4; ++q) {
                unsigned long long a2[4];
#pragma unroll
                for (int i = 0; i < 4; ++i) a2[i] = pack2(avv[i][q], avv[i][q]);
                const int kk = k4 * 4 + q;
#pragma unroll
                for (int g = 0; g < 4; ++g) {
                    ulonglong2 bb = *(const ulonglong2*)&sB[cur][kk * L_ + tx * 4 + g * 64];
#pragma unroll
                    for (int i = 0; i < 4; ++i) {
                        acc2[i][g * 2 + 0] = fma2(a2[i], bb.x, acc2[i][g * 2 + 0]);
                        acc2[i][g * 2 + 1] = fma2(a2[i], bb.y, acc2[i][g * 2 + 1]);
                    }
                }
            }
        }
        __syncthreads();
    }
}

// ---------------- k1: preK = [origin ; P] @ Wk ----------------
__global__ void __launch_bounds__(256, 2)
k1_preK(const float* __restrict__ x, const float* __restrict__ Wk, const float* __restrict__ P) {
    __shared__ __align__(16) float sA[2][SW * 16];
    __shared__ __align__(16) float sB[2][16 * L_];
    const int h = blockIdx.x, mt = blockIdx.y;
    const int t = threadIdx.x, tx = t & 15, ty = t >> 4;
    const float* base; int stride;
    if (mt < 32) { base = x + (size_t)mt * 64 * SD; stride = SD; }
    else         { base = P; stride = D_; }
    unsigned long long acc2[4][8];
#pragma unroll
    for (int i = 0; i < 4; ++i)
#pragma unroll
        for (int p = 0; p < 8; ++p) acc2[i][p] = 0ull;
    gemm64x256<16>(base, stride, Wk + h * (D_ * L_), acc2, sA, sB, t, tx, ty);
#pragma unroll
    for (int i = 0; i < 4; ++i) {
        const size_t row = (size_t)mt * 64 + ty * 4 + i;
        float* dst = g_A + row * HL + h * L_ + tx * 4;
#pragma unroll
        for (int g = 0; g < 4; ++g)
#pragma unroll
            for (int hf = 0; hf < 2; ++hf) {
                float f0, f1;
                unpack2(acc2[i][g * 2 + hf], f0, f1);
                dst[g * 64 + hf * 2 + 0] = f0;
                dst[g * 64 + hf * 2 + 1] = f1;
            }
    }
}

// ---------------- k2: HMMA fused q/score/softmax/v ----------------
__global__ void __launch_bounds__(256, 1)
k2_mma(const float* __restrict__ Wsc) {
    extern __shared__ char smem[];
    float* smf = (float*)smem;
    const int h = blockIdx.x, bt = blockIdx.y;
    const int t = threadIdx.x, w = t >> 5, l = t & 31;
    const int wm = w & 3, wn = w >> 2, grp = l >> 2, qd = l & 3;

    // ---- stage ok / wsc / kp ----
    smf[SM_OK / 4 + t]       = g_A[(size_t)(bt * 2)     * HL + h * L_ + t];
    smf[SM_OK / 4 + 256 + t] = g_A[(size_t)(bt * 2 + 1) * HL + h * L_ + t];
    smf[SM_WSC / 4 + t]      = Wsc[h * L_ + t];
#pragma unroll
    for (int i = 0; i < 16; ++i) {
        const int idx = i * 256 + t;
        const int col = idx >> 4, sg = (idx & 15) * 4;
        float4 v = *(const float4*)(g_kP + (size_t)(h * L_ + col) * 64 + sg);
        *(float4*)(smf + SM_KP / 4 + col * KPSTR + sg) = v;
    }

    const size_t arow0 = (size_t)bt * 128;

    auto issue_chunk = [&](int c, int buf, const __half* Bhg, const __half* Blg) {
        char* bb = smem + buf * BUF_SZ;
#pragma unroll
        for (int i = 0; i < 2; ++i) {
            const int idx = i * 256 + t, r = idx >> 2, kg = idx & 3;
            const size_t so = (arow0 + r) * D_ + c * KCH + kg * 8;
            const uint32_t dofs = r * (ASTR * 2) + kg * 16;
            cp16(bb + OFF_AH + dofs, g_walk_hi + so);
            cp16(bb + OFF_AL + dofs, g_walk_lo + so);
        }
#pragma unroll
        for (int i = 0; i < 4; ++i) {
            const int idx = i * 256 + t, r = idx >> 2, kg = idx & 3;
            const size_t so = (size_t)(h * L_ + r) * D_ + c * KCH + kg * 8;
            const uint32_t dofs = r * (ASTR * 2) + kg * 16;
            cp16(bb + OFF_BH + dofs, Bhg + so);
            cp16(bb + OFF_BL + dofs, Blg + so);
        }
        cp_commit();
    };

    float acc[2][16][4];

    auto compute_chunk = [&](int buf) {
        const char* bb = smem + buf * BUF_SZ;
#pragma unroll
        for (int k16 = 0; k16 < 2; ++k16) {
            const int kb = k16 * 32 + qd * 4;   // byte offset of this lane's k-pair
            uint32_t ah[2][4], al[2][4];
#pragma unroll
            for (int mt = 0; mt < 2; ++mt) {
                const uint32_t ro = (wm * 32 + mt * 16 + grp) * (ASTR * 2);
                ah[mt][0] = *(const uint32_t*)(bb + OFF_AH + ro + kb);
                ah[mt][1] = *(const uint32_t*)(bb + OFF_AH + ro + 8 * (ASTR * 2) + kb);
                ah[mt][2] = *(const uint32_t*)(bb + OFF_AH + ro + kb + 16);
                ah[mt][3] = *(const uint32_t*)(bb + OFF_AH + ro + 8 * (ASTR * 2) + kb + 16);
                al[mt][0] = *(const uint32_t*)(bb + OFF_AL + ro + kb);
                al[mt][1] = *(const uint32_t*)(bb + OFF_AL + ro + 8 * (ASTR * 2) + kb);
                al[mt][2] = *(const uint32_t*)(bb + OFF_AL + ro + kb + 16);
                al[mt][3] = *(const uint32_t*)(bb + OFF_AL + ro + 8 * (ASTR * 2) + kb + 16);
            }
#pragma unroll
            for (int nt = 0; nt < 16; ++nt) {
                const uint32_t no = (wn * 128 + nt * 8 + grp) * (ASTR * 2);
                const uint32_t bh0 = *(const uint32_t*)(bb + OFF_BH + no + kb);
                const uint32_t bh1 = *(const uint32_t*)(bb + OFF_BH + no + kb + 16);
                const uint32_t bl0 = *(const uint32_t*)(bb + OFF_BL + no + kb);
                const uint32_t bl1 = *(const uint32_t*)(bb + OFF_BL + no + kb + 16);
                mma16816(acc[0][nt], ah[0], bh0, bh1);
                mma16816(acc[1][nt], ah[1], bh0, bh1);
                mma16816(acc[0][nt], al[0], bh0, bh1);
                mma16816(acc[1][nt], al[1], bh0, bh1);
                mma16816(acc[0][nt], ah[0], bl0, bl1);
                mma16816(acc[1][nt], ah[1], bl0, bl1);
            }
        }
    };

#pragma unroll 1
    for (int pass = 0; pass < 2; ++pass) {
        const __half* Bhg = pass ? g_wv_hi : g_wq_hi;
        const __half* Blg = pass ? g_wv_lo : g_wq_lo;
#pragma unroll
        for (int mt = 0; mt < 2; ++mt)
#pragma unroll
            for (int nt = 0; nt < 16; ++nt)
#pragma unroll
                for (int e = 0; e < 4; ++e) acc[mt][nt][e] = 0.f;

        issue_chunk(0, 0, Bhg, Blg);
#pragma unroll 1
        for (int c = 0; c < 8; ++c) {
            cp_wait<0>();
            __syncthreads();
            if (c < 7) issue_chunk(c + 1, (c + 1) & 1, Bhg, Blg);
            compute_chunk(c & 1);
        }

        if (pass == 0) {
            // ---- q epilogue: scores ----
            const float* kp = smf + SM_KP / 4;
            const float* ok = smf + SM_OK / 4;
            const float* ws = smf + SM_WSC / 4;
            float ps[4];
#pragma unroll
            for (int mt = 0; mt < 2; ++mt)
#pragma unroll
                for (int rh = 0; rh < 2; ++rh) {
                    const int row = wm * 32 + mt * 16 + rh * 8 + grp;
                    const int s = row & 63, bloc = row >> 6;
                    float a = 0.f;
#pragma unroll
                    for (int nt = 0; nt < 16; ++nt) {
                        const int col = wn * 128 + nt * 8 + qd * 2;
#pragma unroll
                        for (int cj = 0; cj < 2; ++cj) {
                            const float kv = sigf(ok[bloc * 256 + col + cj] + kp[(col + cj) * KPSTR + s]);
                            const float qv = sigf(acc[mt][nt][rh * 2 + cj]);
                            a += __cosf(qv * kv) * ws[col + cj];
                        }
                    }
                    ps[mt * 2 + rh] = a;
                }
#pragma unroll
            for (int j = 0; j < 4; ++j) {
                ps[j] += __shfl_xor_sync(0xffffffffu, ps[j], 1);
                ps[j] += __shfl_xor_sync(0xffffffffu, ps[j], 2);
            }
            if (qd == 0) {
#pragma unroll
                for (int j = 0; j < 4; ++j) {
                    const int row = wm * 32 + (j >> 1) * 16 + (j & 1) * 8 + grp;
                    smf[SM_SP / 4 + wn * 128 + row] = ps[j];
                }
            }
            __syncthreads();
            if (w < 2) {
                const float* sp = smf + SM_SP / 4;
                const int base = w * 64;
                float v0 = sp[base + l] + sp[128 + base + l];
                float v1 = sp[base + 32 + l] + sp[128 + base + 32 + l];
                float mx = fmaxf(v0, v1);
#pragma unroll
                for (int o = 16; o; o >>= 1) mx = fmaxf(mx, __shfl_xor_sync(0xffffffffu, mx, o));
                const float e0 = __expf(v0 - mx), e1 = __expf(v1 - mx);
                float sm = e0 + e1;
#pragma unroll
                for (int o = 16; o; o >>= 1) sm += __shfl_xor_sync(0xffffffffu, sm, o);
                smf[SM_WGT / 4 + base + l] = e0;
                smf[SM_WGT / 4 + base + 32 + l] = e1;
                if (l == 0) smf[SM_INV / 4 + w] = __fdividef(1.f, sm);
            }
            __syncthreads();
        } else {
            // ---- v epilogue: weighted column sums ----
            float w4[4];
#pragma unroll
            for (int j = 0; j < 4; ++j)
                w4[j] = smf[SM_WGT / 4 + wm * 32 + (j >> 1) * 16 + (j & 1) * 8 + grp];
#pragma unroll
            for (int nt = 0; nt < 16; ++nt) {
                float cs0 = 0.f, cs1 = 0.f;
#pragma unroll
                for (int mt = 0; mt < 2; ++mt)
#pragma unroll
                    for (int rh = 0; rh < 2; ++rh) {
                        cs0 += w4[mt * 2 + rh] * sigf(acc[mt][nt][rh * 2 + 0]);
                        cs1 += w4[mt * 2 + rh] * sigf(acc[mt][nt][rh * 2 + 1]);
                    }
#pragma unroll
                for (int o = 4; o <= 16; o <<= 1) {
                    cs0 += __shfl_xor_sync(0xffffffffu, cs0, o);
                    cs1 += __shfl_xor_sync(0xffffffffu, cs1, o);
                }
                if (grp == 0) {
                    const int col = wn * 128 + nt * 8 + qd * 2;
                    smf[SM_VP / 4 + wm * 256 + col]     = cs0;
                    smf[SM_VP / 4 + wm * 256 + col + 1] = cs1;
                }
            }
            __syncthreads();
            const float* vp = smf + SM_VP / 4;
            const float i0 = smf[SM_INV / 4], i1 = smf[SM_INV / 4 + 1];
            g_res[(size_t)(bt * 2)     * HL + h * L_ + t] = (vp[t] + vp[256 + t]) * i0;
            g_res[(size_t)(bt * 2 + 1) * HL + h * L_ + t] = (vp[512 + t] + vp[768 + t]) * i1;
        }
    }
}

// ---------------- k3: out[:, :256] = sigmoid(res @ O) ----------------
__global__ void __launch_bounds__(256, 2)
k3_out(const float* __restrict__ O, float* __restrict__ out) {
    __shared__ __align__(16) float sA[2][SW * 16];
    __shared__ __align__(16) float sB[2][16 * 64];
    const int ct = blockIdx.x, bt = blockIdx.y;
    const int t = threadIdx.x, tx = t & 15, ty = t >> 4;
    const int ar = t >> 2, ac = (t & 3) * 4;
    const int br = t >> 4, bc = (t & 15) * 4;
    const float* rowBase = g_res + (size_t)bt * 64 * HL;

    unsigned long long acc2[4][2];
#pragma unroll
    for (int i = 0; i < 4; ++i) { acc2[i][0] = 0ull; acc2[i][1] = 0ull; }

    cp16(&sA[0][ar * 16 + ac], rowBase + (size_t)ar * HL + ac);
    cp16(&sB[0][br * 64 + bc], O + (size_t)br * D_ + ct * 64 + bc);
    cp_commit();
#pragma unroll 1
    for (int c = 0; c < 128; ++c) {
        const int cur = c & 1;
        if (c + 1 < 128) {
            const int nb = cur ^ 1;
            cp16(&sA[nb][ar * 16 + ac], rowBase + (size_t)ar * HL + (c + 1) * 16 + ac);
            cp16(&sB[nb][br * 64 + bc], O + (size_t)((c + 1) * 16 + br) * D_ + ct * 64 + bc);
            cp_commit();
            cp_wait<1>();
        } else {
            cp_wait<0>();
        }
        __syncthreads();
#pragma unroll
        for (int k4 = 0; k4 < 4; ++k4) {
            float avv[4][4];
#pragma unroll
            for (int i = 0; i < 4; ++i) {
                float4 tmp = *(const float4*)&sA[cur][(ty * 4 + i) * 16 + k4 * 4];
                avv[i][0] = tmp.x; avv[i][1] = tmp.y; avv[i][2] = tmp.z; avv[i][3] = tmp.w;
            }
#pragma unroll
            for (int q = 0; q < 4; ++q) {
                const int kk = k4 * 4 + q;
                ulonglong2 bb = *(const ulonglong2*)&sB[cur][kk * 64 + tx * 4];
#pragma unroll
                for (int i = 0; i < 4; ++i) {
                    unsigned long long a2 = pack2(avv[i][q], avv[i][q]);
                    acc2[i][0] = fma2(a2, bb.x, acc2[i][0]);
                    acc2[i][1] = fma2(a2, bb.y, acc2[i][1]);
                }
            }
        }
        __syncthreads();
    }
#pragma unroll
    for (int i = 0; i < 4; ++i) {
        const size_t bb = (size_t)bt * 64 + ty * 4 + i;
#pragma unroll
        for (int hf = 0; hf < 2; ++hf) {
            float f0, f1;
            unpack2(acc2[i][hf], f0, f1);
            const int d = ct * 64 + tx * 4 + hf * 2;
            out[bb * 512 + d + 0] = sigf(f0);
            out[bb * 512 + d + 1] = sigf(f1);
        }
    }
}

// ---------------- k4: out[:, 256:512] = origin ----------------
__global__ void k4_copy(const float* __restrict__ x, float* __restrict__ out) {
    const int idx = blockIdx.x * 256 + threadIdx.x;
    const int b = idx >> 6, d4 = (idx & 63) * 4;
    float4 v = *(const float4*)(x + (size_t)b * SD + d4);
    *(float4*)(out + (size_t)b * 512 + 256 + d4) = v;
}

// ---------------- launch ----------------
extern "C" void kernel_launch(void* const* d_in, const int* in_sizes, int n_in,
                              void* d_out, int out_size) {
    const float* x  = (const float*)d_in[0];
    const float* Wq = (const float*)d_in[1];
    const float* Wk = (const float*)d_in[2];
    const float* Wv = (const float*)d_in[3];
    const float* W  = (const float*)d_in[4];
    const float* O  = (const float*)d_in[5];
    const float* P  = (const float*)d_in[6];
    // bias cancels under softmax (constant shift per (b,h)); unused.
    float* out = (float*)d_out;

    cudaFuncSetAttribute(k2_mma, cudaFuncAttributeMaxDynamicSharedMemorySize, SMEM_K2);

    p_walk<<<WROWS * 64 / 256, 256>>>(x);
    p_wt<<<dim3(H_ * L_ * D_ / 256, 2), 256>>>(Wq, Wv);
    k1_preK<<<dim3(H_, 33), 256>>>(x, Wk, P);
    k1t<<<HL * SW / 256, 256>>>();
    k2_mma<<<dim3(H_, B_ / 2), 256, SMEM_K2>>>(W);
    k3_out<<<dim3(4, 32), 256>>>(O, out);
    k4_copy<<<512, 256>>>(x, out);
}

// round 13
// speedup vs baseline: 2.0961x; 1.6448x over previous
#include <cuda_runtime.h>
#include <cuda_fp16.h>
#include <cstdint>
#include <cstddef>

#define B_  2048
#define S_  65
#define SW  64
#define D_  256
#define H_  8
#define L_  256
#define HL  2048
#define SD  (S_*D_)        // 16640
#define WROWS (B_*SW)      // 131072

// ---------------- device scratch ----------------
__device__ __align__(16) float  g_A[(B_ + SW) * HL];   // preK raw preacts (origin rows + P rows)
__device__ __align__(16) float  g_kP[HL * SW];         // P-part transposed: [h*L+l][s]
__device__ __align__(16) float  g_res[B_ * HL];        // attention result
__device__ __align__(16) __half g_walk_hi[WROWS * D_];
__device__ __align__(16) __half g_walk_lo[WROWS * D_];
__device__ __align__(16) __half g_wq_hi[H_ * L_ * D_]; // Wq^T split, [h][l][d]
__device__ __align__(16) __half g_wq_lo[H_ * L_ * D_];
__device__ __align__(16) __half g_wv_hi[H_ * L_ * D_];
__device__ __align__(16) __half g_wv_lo[H_ * L_ * D_];

// ---------------- helpers ----------------
__device__ __forceinline__ float sigf(float x) {
    return __fdividef(1.0f, 1.0f + __expf(-x));
}
__device__ __forceinline__ unsigned long long pack2(float x, float y) {
    unsigned long long r;
    asm("mov.b64 %0, {%1, %2};" : "=l"(r) : "f"(x), "f"(y));
    return r;
}
__device__ __forceinline__ void unpack2(unsigned long long v, float& x, float& y) {
    asm("mov.b64 {%0, %1}, %2;" : "=f"(x), "=f"(y) : "l"(v));
}
__device__ __forceinline__ unsigned long long fma2(unsigned long long a, unsigned long long b,
                                                   unsigned long long c) {
    unsigned long long d;
    asm("fma.rn.f32x2 %0, %1, %2, %3;" : "=l"(d) : "l"(a), "l"(b), "l"(c));
    return d;
}
__device__ __forceinline__ void cp16(void* s, const void* g) {
    unsigned sa = (unsigned)__cvta_generic_to_shared(s);
    asm volatile("cp.async.cg.shared.global [%0], [%1], 16;\n" ::"r"(sa), "l"(g));
}
__device__ __forceinline__ void cp_commit() { asm volatile("cp.async.commit_group;\n"); }
template <int N>
__device__ __forceinline__ void cp_wait() { asm volatile("cp.async.wait_group %0;\n" ::"n"(N)); }

__device__ __forceinline__ uint32_t smem_u32(const void* p) {
    uint32_t a;
    asm("{ .reg .u64 t0; cvta.to.shared.u64 t0, %1; cvt.u32.u64 %0, t0; }" : "=r"(a) : "l"(p));
    return a;
}

// m16n8k16 fp16 -> fp32 mma, D accumulates in place
__device__ __forceinline__ void mma16816(float* c, const uint32_t* a, uint32_t b0, uint32_t b1) {
    asm volatile("mma.sync.aligned.m16n8k16.row.col.f32.f16.f16.f32 "
        "{%0,%1,%2,%3}, {%4,%5,%6,%7}, {%8,%9}, {%0,%1,%2,%3};"
        : "+f"(c[0]), "+f"(c[1]), "+f"(c[2]), "+f"(c[3])
        : "r"(a[0]), "r"(a[1]), "r"(a[2]), "r"(a[3]), "r"(b0), "r"(b1));
}
__device__ __forceinline__ void ldsm4(uint32_t* r, uint32_t addr) {
    asm volatile("ldmatrix.sync.aligned.m8n8.x4.shared.b16 {%0,%1,%2,%3}, [%4];"
        : "=r"(r[0]), "=r"(r[1]), "=r"(r[2]), "=r"(r[3]) : "r"(addr));
}

// ---------------- k2 smem layout (bytes) ----------------
#define KCH   32
#define RSTRB 80                        // padded row stride bytes (32 halves + 16B pad)
#define BUF_A (128*RSTRB)               // 10240
#define BUF_B (256*RSTRB)               // 20480
#define OFF_AH 0
#define OFF_AL BUF_A
#define OFF_BH (2*BUF_A)
#define OFF_BL (2*BUF_A + BUF_B)
#define BUF_SZ (2*BUF_A + 2*BUF_B)      // 61440
#define KPSTR  68
#define SM_KP  (2*BUF_SZ)               // 122880
#define SM_OK  (SM_KP + 256*KPSTR*4)    // 192512 ([2][256] f32)
#define SM_WSC (SM_OK + 2048)           // 194560 ([256] f32)
#define SM_SP  (SM_WSC + 1024)          // 195584 ([4][128] f32)
#define SM_WGT (SM_SP + 2048)           // 197632 ([128] f32)
#define SM_VP  (SM_WGT + 512)           // 198144 ([4][256] f32)
#define SM_INV (SM_VP + 4096)           // 202240
#define SMEM_K2 202256

// ---------------- prep: split walk rows into fp16 hi/lo ----------------
__global__ void p_walk(const float* __restrict__ x) {
    const int idx = blockIdx.x * 256 + threadIdx.x;
    const int row = idx >> 6, c4 = (idx & 63) * 4;
    const int b = row >> 6, s = row & 63;
    float4 v = *(const float4*)(x + (size_t)b * SD + (size_t)(s + 1) * D_ + c4);
    __half h0 = __float2half_rn(v.x), h1 = __float2half_rn(v.y);
    __half h2 = __float2half_rn(v.z), h3 = __float2half_rn(v.w);
    const size_t o = (size_t)row * D_ + c4;
    *(__half2*)(g_walk_hi + o)     = __halves2half2(h0, h1);
    *(__half2*)(g_walk_hi + o + 2) = __halves2half2(h2, h3);
    *(__half2*)(g_walk_lo + o)     = __halves2half2(__float2half_rn(v.x - __half2float(h0)),
                                                    __float2half_rn(v.y - __half2float(h1)));
    *(__half2*)(g_walk_lo + o + 2) = __halves2half2(__float2half_rn(v.z - __half2float(h2)),
                                                    __float2half_rn(v.w - __half2float(h3)));
}

// ---------------- prep: transpose + split weights (h,d,l) -> (h,l,d) ----------------
__global__ void p_wt(const float* __restrict__ Wq, const float* __restrict__ Wv) {
    const int idx = blockIdx.x * 256 + threadIdx.x;
    const int h = idx >> 16, l = (idx >> 8) & 255, d = idx & 255;
    const float* src = (blockIdx.y == 0) ? Wq : Wv;
    float v = src[(size_t)h * 65536 + (size_t)d * 256 + l];
    __half hi = __float2half_rn(v);
    __half lo = __float2half_rn(v - __half2float(hi));
    if (blockIdx.y == 0) { g_wq_hi[idx] = hi; g_wq_lo[idx] = lo; }
    else                 { g_wv_hi[idx] = hi; g_wv_lo[idx] = lo; }
}

// ---------------- k1t: transpose P-part of preK into [hl][s] ----------------
__global__ void k1t(void) {
    const int idx = blockIdx.x * 256 + threadIdx.x;
    const int hl = idx >> 6, s = idx & 63;
    g_kP[idx] = g_A[(size_t)(B_ + s) * HL + hl];
}

// ---------------- fp32 GEMM core (k1, k3) ----------------
template <int NCH>
__device__ __forceinline__ void gemm64x256(const float* __restrict__ rowBase, int rowStride,
                                           const float* __restrict__ Wg,
                                           unsigned long long (&acc2)[4][8],
                                           float (&sA)[2][SW * 16], float (&sB)[2][16 * L_],
                                           int t, int tx, int ty) {
    const int ar = t >> 2, ac = (t & 3) * 4;
    const int br = t >> 4, bc = (t & 15) * 16;
    {
        cp16(&sA[0][ar * 16 + ac], rowBase + (size_t)ar * rowStride + ac);
        const float* src = Wg + (size_t)br * L_ + bc;
        float* dst = &sB[0][br * L_ + bc];
        cp16(dst + 0, src + 0); cp16(dst + 4, src + 4);
        cp16(dst + 8, src + 8); cp16(dst + 12, src + 12);
        cp_commit();
    }
#pragma unroll 1
    for (int c = 0; c < NCH; ++c) {
        const int cur = c & 1;
        if (c + 1 < NCH) {
            const int nb = cur ^ 1;
            cp16(&sA[nb][ar * 16 + ac], rowBase + (size_t)ar * rowStride + (c + 1) * 16 + ac);
            const float* src = Wg + (size_t)((c + 1) * 16 + br) * L_ + bc;
            float* dst = &sB[nb][br * L_ + bc];
            cp16(dst + 0, src + 0); cp16(dst + 4, src + 4);
            cp16(dst + 8, src + 8); cp16(dst + 12, src + 12);
            cp_commit();
            cp_wait<1>();
        } else {
            cp_wait<0>();
        }
        __syncthreads();
#pragma unroll
        for (int k4 = 0; k4 < 4; ++k4) {
            float avv[4][4];
#pragma unroll
            for (int i = 0; i < 4; ++i) {
                float4 tmp = *(const float4*)&sA[cur][(ty * 4 + i) * 16 + k4 * 4];
                avv[i][0] = tmp.x; avv[i][1] = tmp.y; avv[i][2] = tmp.z; avv[i][3] = tmp.w;
            }
#pragma unroll
            for (int q = 0; q < 4; ++q) {
                unsigned long long a2[4];
#pragma unroll
                for (int i = 0; i < 4; ++i) a2[i] = pack2(avv[i][q], avv[i][q]);
                const int kk = k4 * 4 + q;
#pragma unroll
                for (int g = 0; g < 4; ++g) {
                    ulonglong2 bb = *(const ulonglong2*)&sB[cur][kk * L_ + tx * 4 + g * 64];
#pragma unroll
                    for (int i = 0; i < 4; ++i) {
                        acc2[i][g * 2 + 0] = fma2(a2[i], bb.x, acc2[i][g * 2 + 0]);
                        acc2[i][g * 2 + 1] = fma2(a2[i], bb.y, acc2[i][g * 2 + 1]);
                    }
                }
            }
        }
        __syncthreads();
    }
}

// ---------------- k1: preK = [origin ; P] @ Wk ----------------
__global__ void __launch_bounds__(256, 2)
k1_preK(const float* __restrict__ x, const float* __restrict__ Wk, const float* __restrict__ P) {
    __shared__ __align__(16) float sA[2][SW * 16];
    __shared__ __align__(16) float sB[2][16 * L_];
    const int h = blockIdx.x, mt = blockIdx.y;
    const int t = threadIdx.x, tx = t & 15, ty = t >> 4;
    const float* base; int stride;
    if (mt < 32) { base = x + (size_t)mt * 64 * SD; stride = SD; }
    else         { base = P; stride = D_; }
    unsigned long long acc2[4][8];
#pragma unroll
    for (int i = 0; i < 4; ++i)
#pragma unroll
        for (int p = 0; p < 8; ++p) acc2[i][p] = 0ull;
    gemm64x256<16>(base, stride, Wk + h * (D_ * L_), acc2, sA, sB, t, tx, ty);
#pragma unroll
    for (int i = 0; i < 4; ++i) {
        const size_t row = (size_t)mt * 64 + ty * 4 + i;
        float* dst = g_A + row * HL + h * L_ + tx * 4;
#pragma unroll
        for (int g = 0; g < 4; ++g)
#pragma unroll
            for (int hf = 0; hf < 2; ++hf) {
                float f0, f1;
                unpack2(acc2[i][g * 2 + hf], f0, f1);
                dst[g * 64 + hf * 2 + 0] = f0;
                dst[g * 64 + hf * 2 + 1] = f1;
            }
    }
}

// ---------------- k2: HMMA fused q/score/softmax/v (512 thr, ldmatrix) ----------------
__global__ void __launch_bounds__(512, 1)
k2_mma(const float* __restrict__ Wsc) {
    extern __shared__ char smem[];
    float* smf = (float*)smem;
    const uint32_t sbase = smem_u32(smem);
    const int h = blockIdx.x, bt = blockIdx.y;
    const int t = threadIdx.x, w = t >> 5, l = t & 31;
    const int wm = w & 3, wn = w >> 2;        // wm: 32-row strip, wn: 64-col strip
    const int grp = l >> 2, qd = l & 3;
    const int lr = l & 7, quad = l >> 3;

    // ---- stage ok / wsc / kp ----
    smf[SM_OK / 4 + t] = g_A[(size_t)(bt * 2 + (t >> 8)) * HL + h * L_ + (t & 255)];
    if (t < 256) smf[SM_WSC / 4 + t] = Wsc[h * L_ + t];
#pragma unroll
    for (int i = 0; i < 8; ++i) {
        const int idx = i * 512 + t;
        const int col = idx >> 4, sg = (idx & 15) * 4;
        float4 v = *(const float4*)(g_kP + (size_t)(h * L_ + col) * 64 + sg);
        *(float4*)(smf + SM_KP / 4 + col * KPSTR + sg) = v;
    }

    const size_t arow0 = (size_t)bt * 128;

    // ldmatrix lane-address offsets (bytes, relative to matrix base in buffer)
    uint32_t aoff[2], boff[4];
#pragma unroll
    for (int mt = 0; mt < 2; ++mt)
        aoff[mt] = (uint32_t)(wm * 32 + mt * 16 + (quad & 1) * 8 + lr) * RSTRB + (quad >> 1) * 16;
#pragma unroll
    for (int ng = 0; ng < 4; ++ng)
        boff[ng] = (uint32_t)(wn * 64 + ng * 16 + (quad >> 1) * 8 + lr) * RSTRB + (quad & 1) * 16;

    auto issue_chunk = [&](int c, int buf, const __half* Bhg, const __half* Blg) {
        char* bb = smem + buf * BUF_SZ;
        {
            const int r = t >> 2, kg = t & 3;
            const size_t so = (arow0 + r) * D_ + c * KCH + kg * 8;
            const uint32_t dofs = r * RSTRB + kg * 16;
            cp16(bb + OFF_AH + dofs, g_walk_hi + so);
            cp16(bb + OFF_AL + dofs, g_walk_lo + so);
        }
#pragma unroll
        for (int i = 0; i < 2; ++i) {
            const int idx = i * 512 + t, r = idx >> 2, kg = idx & 3;
            const size_t so = (size_t)(h * L_ + r) * D_ + c * KCH + kg * 8;
            const uint32_t dofs = r * RSTRB + kg * 16;
            cp16(bb + OFF_BH + dofs, Bhg + so);
            cp16(bb + OFF_BL + dofs, Blg + so);
        }
        cp_commit();
    };

    float acc[2][8][4];
#pragma unroll
    for (int mt = 0; mt < 2; ++mt)
#pragma unroll
        for (int nt = 0; nt < 8; ++nt)
#pragma unroll
            for (int e = 0; e < 4; ++e) acc[mt][nt][e] = 0.f;

    auto compute_chunk = [&](int buf) {
        const uint32_t bbase = sbase + buf * BUF_SZ;
#pragma unroll
        for (int k16 = 0; k16 < 2; ++k16) {
            const uint32_t ko = k16 * 32;
            uint32_t ah[2][4], al[2][4];
#pragma unroll
            for (int mt = 0; mt < 2; ++mt) {
                ldsm4(ah[mt], bbase + OFF_AH + aoff[mt] + ko);
                ldsm4(al[mt], bbase + OFF_AL + aoff[mt] + ko);
            }
#pragma unroll
            for (int ng = 0; ng < 4; ++ng) {
                uint32_t bh[4], bl[4];
                ldsm4(bh, bbase + OFF_BH + boff[ng] + ko);
                ldsm4(bl, bbase + OFF_BL + boff[ng] + ko);
#pragma unroll
                for (int sub = 0; sub < 2; ++sub) {
                    const int nt = ng * 2 + sub;
                    const uint32_t b0 = bh[sub * 2], b1 = bh[sub * 2 + 1];
                    const uint32_t c0 = bl[sub * 2], c1 = bl[sub * 2 + 1];
                    mma16816(acc[0][nt], ah[0], b0, b1);
                    mma16816(acc[1][nt], ah[1], b0, b1);
                    mma16816(acc[0][nt], al[0], b0, b1);
                    mma16816(acc[1][nt], al[1], b0, b1);
                    mma16816(acc[0][nt], ah[0], c0, c1);
                    mma16816(acc[1][nt], ah[1], c0, c1);
                }
            }
        }
    };

    issue_chunk(0, 0, g_wq_hi, g_wq_lo);
#pragma unroll 1
    for (int cc = 0; cc < 16; ++cc) {
        cp_wait<0>();
        __syncthreads();
        if (cc < 15) {
            const int nc = cc + 1;
            issue_chunk(nc & 7, nc & 1, (nc >> 3) ? g_wv_hi : g_wq_hi,
                        (nc >> 3) ? g_wv_lo : g_wq_lo);
        }
        compute_chunk(cc & 1);

        if (cc == 7) {
            // ---- q epilogue: scores (overlaps pass-1 chunk-0 cp.async) ----
            const float* kp = smf + SM_KP / 4;
            const float* ok = smf + SM_OK / 4;
            const float* ws = smf + SM_WSC / 4;
            float ps[4];
#pragma unroll
            for (int mt = 0; mt < 2; ++mt)
#pragma unroll
                for (int rh = 0; rh < 2; ++rh) {
                    const int row = wm * 32 + mt * 16 + rh * 8 + grp;
                    const int s = row & 63, bloc = row >> 6;
                    float a = 0.f;
#pragma unroll
                    for (int nt = 0; nt < 8; ++nt) {
                        const int col = wn * 64 + nt * 8 + qd * 2;
#pragma unroll
                        for (int cj = 0; cj < 2; ++cj) {
                            const float kv = sigf(ok[bloc * 256 + col + cj] + kp[(col + cj) * KPSTR + s]);
                            const float qv = sigf(acc[mt][nt][rh * 2 + cj]);
                            a += __cosf(qv * kv) * ws[col + cj];
                        }
                    }
                    ps[mt * 2 + rh] = a;
                }
#pragma unroll
            for (int j = 0; j < 4; ++j) {
                ps[j] += __shfl_xor_sync(0xffffffffu, ps[j], 1);
                ps[j] += __shfl_xor_sync(0xffffffffu, ps[j], 2);
            }
            if (qd == 0) {
#pragma unroll
                for (int j = 0; j < 4; ++j) {
                    const int row = wm * 32 + (j >> 1) * 16 + (j & 1) * 8 + grp;
                    smf[SM_SP / 4 + wn * 128 + row] = ps[j];
                }
            }
            __syncthreads();
            if (w < 2) {
                const float* sp = smf + SM_SP / 4;
                const int base = w * 64;
                float v0 = sp[base + l] + sp[128 + base + l] + sp[256 + base + l] + sp[384 + base + l];
                float v1 = sp[base + 32 + l] + sp[128 + base + 32 + l] + sp[256 + base + 32 + l] + sp[384 + base + 32 + l];
                float mx = fmaxf(v0, v1);
#pragma unroll
                for (int o = 16; o; o >>= 1) mx = fmaxf(mx, __shfl_xor_sync(0xffffffffu, mx, o));
                const float e0 = __expf(v0 - mx), e1 = __expf(v1 - mx);
                float sm = e0 + e1;
#pragma unroll
                for (int o = 16; o; o >>= 1) sm += __shfl_xor_sync(0xffffffffu, sm, o);
                smf[SM_WGT / 4 + base + l] = e0;
                smf[SM_WGT / 4 + base + 32 + l] = e1;
                if (l == 0) smf[SM_INV / 4 + w] = __fdividef(1.f, sm);
            }
            __syncthreads();
#pragma unroll
            for (int mt = 0; mt < 2; ++mt)
#pragma unroll
                for (int nt = 0; nt < 8; ++nt)
#pragma unroll
                    for (int e = 0; e < 4; ++e) acc[mt][nt][e] = 0.f;
        }
    }

    // ---- v epilogue: weighted column sums ----
    float w4[4];
#pragma unroll
    for (int j = 0; j < 4; ++j)
        w4[j] = smf[SM_WGT / 4 + wm * 32 + (j >> 1) * 16 + (j & 1) * 8 + grp];
#pragma unroll
    for (int nt = 0; nt < 8; ++nt) {
        float cs0 = 0.f, cs1 = 0.f;
#pragma unroll
        for (int j = 0; j < 4; ++j) {
            cs0 += w4[j] * sigf(acc[j >> 1][nt][(j & 1) * 2 + 0]);
            cs1 += w4[j] * sigf(acc[j >> 1][nt][(j & 1) * 2 + 1]);
        }
#pragma unroll
        for (int o = 4; o <= 16; o <<= 1) {
            cs0 += __shfl_xor_sync(0xffffffffu, cs0, o);
            cs1 += __shfl_xor_sync(0xffffffffu, cs1, o);
        }
        if (grp == 0) {
            const int col = wn * 64 + nt * 8 + qd * 2;
            smf[SM_VP / 4 + wm * 256 + col]     = cs0;
            smf[SM_VP / 4 + wm * 256 + col + 1] = cs1;
        }
    }
    __syncthreads();
    {
        const float* vp = smf + SM_VP / 4;
        const int bloc = t >> 8, col = t & 255;
        const float inv = smf[SM_INV / 4 + bloc];
        const float r = (vp[bloc * 512 + col] + vp[bloc * 512 + 256 + col]) * inv;
        g_res[(size_t)(bt * 2 + bloc) * HL + h * L_ + col] = r;
    }
}

// ---------------- k3: out[:, :256] = sigmoid(res @ O) ----------------
__global__ void __launch_bounds__(256, 2)
k3_out(const float* __restrict__ O, float* __restrict__ out) {
    __shared__ __align__(16) float sA[2][SW * 16];
    __shared__ __align__(16) float sB[2][16 * 64];
    const int ct = blockIdx.x, bt = blockIdx.y;
    const int t = threadIdx.x, tx = t & 15, ty = t >> 4;
    const int ar = t >> 2, ac = (t & 3) * 4;
    const int br = t >> 4, bc = (t & 15) * 4;
    const float* rowBase = g_res + (size_t)bt * 64 * HL;

    unsigned long long acc2[4][2];
#pragma unroll
    for (int i = 0; i < 4; ++i) { acc2[i][0] = 0ull; acc2[i][1] = 0ull; }

    cp16(&sA[0][ar * 16 + ac], rowBase + (size_t)ar * HL + ac);
    cp16(&sB[0][br * 64 + bc], O + (size_t)br * D_ + ct * 64 + bc);
    cp_commit();
#pragma unroll 1
    for (int c = 0; c < 128; ++c) {
        const int cur = c & 1;
        if (c + 1 < 128) {
            const int nb = cur ^ 1;
            cp16(&sA[nb][ar * 16 + ac], rowBase + (size_t)ar * HL + (c + 1) * 16 + ac);
            cp16(&sB[nb][br * 64 + bc], O + (size_t)((c + 1) * 16 + br) * D_ + ct * 64 + bc);
            cp_commit();
            cp_wait<1>();
        } else {
            cp_wait<0>();
        }
        __syncthreads();
#pragma unroll
        for (int k4 = 0; k4 < 4; ++k4) {
            float avv[4][4];
#pragma unroll
            for (int i = 0; i < 4; ++i) {
                float4 tmp = *(const float4*)&sA[cur][(ty * 4 + i) * 16 + k4 * 4];
                avv[i][0] = tmp.x; avv[i][1] = tmp.y; avv[i][2] = tmp.z; avv[i][3] = tmp.w;
            }
#pragma unroll
            for (int q = 0; q < 4; ++q) {
                const int kk = k4 * 4 + q;
                ulonglong2 bb = *(const ulonglong2*)&sB[cur][kk * 64 + tx * 4];
#pragma unroll
                for (int i = 0; i < 4; ++i) {
                    unsigned long long a2 = pack2(avv[i][q], avv[i][q]);
                    acc2[i][0] = fma2(a2, bb.x, acc2[i][0]);
                    acc2[i][1] = fma2(a2, bb.y, acc2[i][1]);
                }
            }
        }
        __syncthreads();
    }
#pragma unroll
    for (int i = 0; i < 4; ++i) {
        const size_t bb = (size_t)bt * 64 + ty * 4 + i;
#pragma unroll
        for (int hf = 0; hf < 2; ++hf) {
            float f0, f1;
            unpack2(acc2[i][hf], f0, f1);
            const int d = ct * 64 + tx * 4 + hf * 2;
            out[bb * 512 + d + 0] = sigf(f0);
            out[bb * 512 + d + 1] = sigf(f1);
        }
    }
}

// ---------------- k4: out[:, 256:512] = origin ----------------
__global__ void k4_copy(const float* __restrict__ x, float* __restrict__ out) {
    const int idx = blockIdx.x * 256 + threadIdx.x;
    const int b = idx >> 6, d4 = (idx & 63) * 4;
    float4 v = *(const float4*)(x + (size_t)b * SD + d4);
    *(float4*)(out + (size_t)b * 512 + 256 + d4) = v;
}

// ---------------- launch ----------------
extern "C" void kernel_launch(void* const* d_in, const int* in_sizes, int n_in,
                              void* d_out, int out_size) {
    const float* x  = (const float*)d_in[0];
    const float* Wq = (const float*)d_in[1];
    const float* Wk = (const float*)d_in[2];
    const float* Wv = (const float*)d_in[3];
    const float* W  = (const float*)d_in[4];
    const float* O  = (const float*)d_in[5];
    const float* P  = (const float*)d_in[6];
    // bias cancels under softmax (constant shift per (b,h)); unused.
    float* out = (float*)d_out;

    cudaFuncSetAttribute(k2_mma, cudaFuncAttributeMaxDynamicSharedMemorySize, SMEM_K2);

    p_walk<<<WROWS * 64 / 256, 256>>>(x);
    p_wt<<<dim3(H_ * L_ * D_ / 256, 2), 256>>>(Wq, Wv);
    k1_preK<<<dim3(H_, 33), 256>>>(x, Wk, P);
    k1t<<<HL * SW / 256, 256>>>();
    k2_mma<<<dim3(H_, B_ / 2), 512, SMEM_K2>>>(W);
    k3_out<<<dim3(4, 32), 256>>>(O, out);
    k4_copy<<<512, 256>>>(x, out);
}

// round 14
// speedup vs baseline: 2.4938x; 1.1898x over previous
#include <cuda_runtime.h>
#include <cuda_fp16.h>
#include <cstdint>
#include <cstddef>

#define B_  2048
#define S_  65
#define SW  64
#define D_  256
#define H_  8
#define L_  256
#define HL  2048
#define SD  (S_*D_)        // 16640
#define WROWS (B_*SW)      // 131072

// chunk-blocked layouts (halves): walk: [bt][c][128 rows][40], weights: [h][c][256 rows][40]
#define WBLK  40960        // per-bt block (8 chunks * 128 * 40)
#define WCHK  5120         // per-chunk (128*40)
#define HBLK  81920        // per-h block (8 chunks * 256 * 40)
#define HCHK  10240        // per-chunk (256*40)

// ---------------- device scratch ----------------
__device__ __align__(16) float  g_A[(B_ + SW) * HL];   // preK raw preacts
__device__ __align__(16) float  g_kP[HL * SW];         // P-part transposed: [h*L+l][s]
__device__ __align__(16) float  g_res[B_ * HL];
__device__ __align__(16) __half g_walk_hi[1024 * WBLK];
__device__ __align__(16) __half g_walk_lo[1024 * WBLK];
__device__ __align__(16) __half g_wq_hi[H_ * HBLK];
__device__ __align__(16) __half g_wq_lo[H_ * HBLK];
__device__ __align__(16) __half g_wv_hi[H_ * HBLK];
__device__ __align__(16) __half g_wv_lo[H_ * HBLK];

// ---------------- helpers ----------------
__device__ __forceinline__ float sigf(float x) {
    return __fdividef(1.0f, 1.0f + __expf(-x));
}
__device__ __forceinline__ unsigned long long pack2(float x, float y) {
    unsigned long long r;
    asm("mov.b64 %0, {%1, %2};" : "=l"(r) : "f"(x), "f"(y));
    return r;
}
__device__ __forceinline__ void unpack2(unsigned long long v, float& x, float& y) {
    asm("mov.b64 {%0, %1}, %2;" : "=f"(x), "=f"(y) : "l"(v));
}
__device__ __forceinline__ unsigned long long fma2(unsigned long long a, unsigned long long b,
                                                   unsigned long long c) {
    unsigned long long d;
    asm("fma.rn.f32x2 %0, %1, %2, %3;" : "=l"(d) : "l"(a), "l"(b), "l"(c));
    return d;
}
__device__ __forceinline__ void cp16(void* s, const void* g) {
    unsigned sa = (unsigned)__cvta_generic_to_shared(s);
    asm volatile("cp.async.cg.shared.global [%0], [%1], 16;\n" ::"r"(sa), "l"(g));
}
__device__ __forceinline__ void cp_commit() { asm volatile("cp.async.commit_group;\n"); }
template <int N>
__device__ __forceinline__ void cp_wait() { asm volatile("cp.async.wait_group %0;\n" ::"n"(N)); }

__device__ __forceinline__ uint32_t smem_u32(const void* p) {
    uint32_t a;
    asm("{ .reg .u64 t0; cvta.to.shared.u64 t0, %1; cvt.u32.u64 %0, t0; }" : "=r"(a) : "l"(p));
    return a;
}

// m16n8k16 fp16 -> fp32 mma
__device__ __forceinline__ void mma16816(float* c, const uint32_t* a, uint32_t b0, uint32_t b1) {
    asm volatile("mma.sync.aligned.m16n8k16.row.col.f32.f16.f16.f32 "
        "{%0,%1,%2,%3}, {%4,%5,%6,%7}, {%8,%9}, {%0,%1,%2,%3};"
        : "+f"(c[0]), "+f"(c[1]), "+f"(c[2]), "+f"(c[3])
        : "r"(a[0]), "r"(a[1]), "r"(a[2]), "r"(a[3]), "r"(b0), "r"(b1));
}
__device__ __forceinline__ void ldsm4(uint32_t* r, uint32_t addr) {
    asm volatile("ldmatrix.sync.aligned.m8n8.x4.shared.b16 {%0,%1,%2,%3}, [%4];"
        : "=r"(r[0]), "=r"(r[1]), "=r"(r[2]), "=r"(r[3]) : "r"(addr));
}

// bulk async copy global -> shared, mbarrier completion (sm_90)
__device__ __forceinline__ void bulkcp(uint32_t dst, const void* src, uint32_t bytes, uint32_t mbar) {
    asm volatile("cp.async.bulk.shared::cluster.global.mbarrier::complete_tx::bytes [%0], [%1], %2, [%3];"
        :: "r"(dst), "l"(src), "r"(bytes), "r"(mbar) : "memory");
}
#define MB_INIT(mb, c)  asm volatile("mbarrier.init.shared.b64 [%0], %1;" :: "r"((uint32_t)(mb)), "r"((uint32_t)(c)) : "memory")
#define MB_EXPECT_TX(mb, n) asm volatile("mbarrier.arrive.expect_tx.shared.b64 _, [%0], %1;" :: "r"((uint32_t)(mb)), "r"((uint32_t)(n)) : "memory")
#define MB_WAIT(mb, par) do { \
    uint32_t _m = (uint32_t)(mb), _p = (uint32_t)(par), _d; \
    asm volatile("{\n\t.reg .pred p;\n\t" \
        "mbarrier.try_wait.parity.acquire.cta.shared::cta.b64 p, [%1], %2;\n\t" \
        "selp.b32 %0, 1, 0, p;\n\t}" : "=r"(_d) : "r"(_m), "r"(_p) : "memory"); \
    if (!_d) { \
        asm volatile("{\n\t.reg .pred P1;\n\t" \
            "WL_%=:\n\t" \
            "mbarrier.try_wait.parity.acquire.cta.shared::cta.b64 P1, [%0], %1, 0x989680;\n\t" \
            "@P1 bra.uni WD_%=;\n\t" \
            "bra.uni WL_%=;\n\t" \
            "WD_%=:\n\t}" :: "r"(_m), "r"(_p) : "memory"); \
    } \
} while (0)

// ---------------- k2 smem layout (bytes) ----------------
#define RSTRB 80
#define OFF_AH 0
#define OFF_AL 10240
#define OFF_BH 20480
#define OFF_BL 40960
#define BUF_SZ 61440
#define SM_MB  122880
#define KPSTR  68
#define SM_KP  122912
#define SM_OK  192544
#define SM_WSC 194592
#define SM_SP  195616
#define SM_WGT 197664
#define SM_VP  198176
#define SM_INV 202272
#define SMEM_K2 202288

// ---------------- prep: split walk rows into fp16 hi/lo (chunk-blocked) ----------------
__global__ void p_walk(const float* __restrict__ x) {
    const int idx = blockIdx.x * 256 + threadIdx.x;
    const int row = idx >> 6, d = (idx & 63) * 4;
    const int b = row >> 6, s = row & 63;
    float4 v = *(const float4*)(x + (size_t)b * SD + (size_t)(s + 1) * D_ + d);
    __half h0 = __float2half_rn(v.x), h1 = __float2half_rn(v.y);
    __half h2 = __float2half_rn(v.z), h3 = __float2half_rn(v.w);
    const int bt = row >> 7, tr = row & 127;
    const size_t o = (size_t)bt * WBLK + (d >> 5) * WCHK + tr * 40 + (d & 31);
    *(__half2*)(g_walk_hi + o)     = __halves2half2(h0, h1);
    *(__half2*)(g_walk_hi + o + 2) = __halves2half2(h2, h3);
    *(__half2*)(g_walk_lo + o)     = __halves2half2(__float2half_rn(v.x - __half2float(h0)),
                                                    __float2half_rn(v.y - __half2float(h1)));
    *(__half2*)(g_walk_lo + o + 2) = __halves2half2(__float2half_rn(v.z - __half2float(h2)),
                                                    __float2half_rn(v.w - __half2float(h3)));
}

// ---------------- prep: transpose + split weights (h,d,l) -> chunk-blocked [h][c][l][40] ----------------
__global__ void p_wt(const float* __restrict__ Wq, const float* __restrict__ Wv) {
    const int idx = blockIdx.x * 256 + threadIdx.x;
    const int h = idx >> 16, l = (idx >> 8) & 255, d = idx & 255;
    const float* src = (blockIdx.y == 0) ? Wq : Wv;
    float v = src[(size_t)h * 65536 + (size_t)d * 256 + l];
    __half hi = __float2half_rn(v);
    __half lo = __float2half_rn(v - __half2float(hi));
    const size_t o = (size_t)h * HBLK + (d >> 5) * HCHK + l * 40 + (d & 31);
    if (blockIdx.y == 0) { g_wq_hi[o] = hi; g_wq_lo[o] = lo; }
    else                 { g_wv_hi[o] = hi; g_wv_lo[o] = lo; }
}

// ---------------- k1t: transpose P-part of preK into [hl][s] ----------------
__global__ void k1t(void) {
    const int idx = blockIdx.x * 256 + threadIdx.x;
    const int hl = idx >> 6, s = idx & 63;
    g_kP[idx] = g_A[(size_t)(B_ + s) * HL + hl];
}

// ---------------- fp32 GEMM core (k1, k3) ----------------
template <int NCH>
__device__ __forceinline__ void gemm64x256(const float* __restrict__ rowBase, int rowStride,
                                           const float* __restrict__ Wg,
                                           unsigned long long (&acc2)[4][8],
                                           float (&sA)[2][SW * 16], float (&sB)[2][16 * L_],
                                           int t, int tx, int ty) {
    const int ar = t >> 2, ac = (t & 3) * 4;
    const int br = t >> 4, bc = (t & 15) * 16;
    {
        cp16(&sA[0][ar * 16 + ac], rowBase + (size_t)ar * rowStride + ac);
        const float* src = Wg + (size_t)br * L_ + bc;
        float* dst = &sB[0][br * L_ + bc];
        cp16(dst + 0, src + 0); cp16(dst + 4, src + 4);
        cp16(dst + 8, src + 8); cp16(dst + 12, src + 12);
        cp_commit();
    }
#pragma unroll 1
    for (int c = 0; c < NCH; ++c) {
        const int cur = c & 1;
        if (c + 1 < NCH) {
            const int nb = cur ^ 1;
            cp16(&sA[nb][ar * 16 + ac], rowBase + (size_t)ar * rowStride + (c + 1) * 16 + ac);
            const float* src = Wg + (size_t)((c + 1) * 16 + br) * L_ + bc;
            float* dst = &sB[nb][br * L_ + bc];
            cp16(dst + 0, src + 0); cp16(dst + 4, src + 4);
            cp16(dst + 8, src + 8); cp16(dst + 12, src + 12);
            cp_commit();
            cp_wait<1>();
        } else {
            cp_wait<0>();
        }
        __syncthreads();
#pragma unroll
        for (int k4 = 0; k4 < 4; ++k4) {
            float avv[4][4];
#pragma unroll
            for (int i = 0; i < 4; ++i) {
                float4 tmp = *(const float4*)&sA[cur][(ty * 4 + i) * 16 + k4 * 4];
                avv[i][0] = tmp.x; avv[i][1] = tmp.y; avv[i][2] = tmp.z; avv[i][3] = tmp.w;
            }
#pragma unroll
            for (int q = 0; q < 4; ++q) {
                unsigned long long a2[4];
#pragma unroll
                for (int i = 0; i < 4; ++i) a2[i] = pack2(avv[i][q], avv[i][q]);
                const int kk = k4 * 4 + q;
#pragma unroll
                for (int g = 0; g < 4; ++g) {
                    ulonglong2 bb = *(const ulonglong2*)&sB[cur][kk * L_ + tx * 4 + g * 64];
#pragma unroll
                    for (int i = 0; i < 4; ++i) {
                        acc2[i][g * 2 + 0] = fma2(a2[i], bb.x, acc2[i][g * 2 + 0]);
                        acc2[i][g * 2 + 1] = fma2(a2[i], bb.y, acc2[i][g * 2 + 1]);
                    }
                }
            }
        }
        __syncthreads();
    }
}

// ---------------- k1: preK = [origin ; P] @ Wk ----------------
__global__ void __launch_bounds__(256, 2)
k1_preK(const float* __restrict__ x, const float* __restrict__ Wk, const float* __restrict__ P) {
    __shared__ __align__(16) float sA[2][SW * 16];
    __shared__ __align__(16) float sB[2][16 * L_];
    const int h = blockIdx.x, mt = blockIdx.y;
    const int t = threadIdx.x, tx = t & 15, ty = t >> 4;
    const float* base; int stride;
    if (mt < 32) { base = x + (size_t)mt * 64 * SD; stride = SD; }
    else         { base = P; stride = D_; }
    unsigned long long acc2[4][8];
#pragma unroll
    for (int i = 0; i < 4; ++i)
#pragma unroll
        for (int p = 0; p < 8; ++p) acc2[i][p] = 0ull;
    gemm64x256<16>(base, stride, Wk + h * (D_ * L_), acc2, sA, sB, t, tx, ty);
#pragma unroll
    for (int i = 0; i < 4; ++i) {
        const size_t row = (size_t)mt * 64 + ty * 4 + i;
        float* dst = g_A + row * HL + h * L_ + tx * 4;
#pragma unroll
        for (int g = 0; g < 4; ++g)
#pragma unroll
            for (int hf = 0; hf < 2; ++hf) {
                float f0, f1;
                unpack2(acc2[i][g * 2 + hf], f0, f1);
                dst[g * 64 + hf * 2 + 0] = f0;
                dst[g * 64 + hf * 2 + 1] = f1;
            }
    }
}

// ---------------- k2: HMMA fused q/score/softmax/v (bulk-copy pipeline) ----------------
__global__ void __launch_bounds__(512, 1)
k2_mma(const float* __restrict__ Wsc) {
    extern __shared__ char smem[];
    float* smf = (float*)smem;
    const uint32_t sbase = smem_u32(smem);
    const int h = blockIdx.x, bt = blockIdx.y;
    const int t = threadIdx.x, w = t >> 5, l = t & 31;
    const int wm = w & 3, wn = w >> 2;
    const int grp = l >> 2, qd = l & 3;
    const int lr = l & 7, quad = l >> 3;

    if (t == 0) { MB_INIT(sbase + SM_MB, 1); MB_INIT(sbase + SM_MB + 8, 1); }

    // ---- stage ok / wsc / kp ----
    smf[SM_OK / 4 + t] = g_A[(size_t)(bt * 2 + (t >> 8)) * HL + h * L_ + (t & 255)];
    if (t < 256) smf[SM_WSC / 4 + t] = Wsc[h * L_ + t];
#pragma unroll
    for (int i = 0; i < 8; ++i) {
        const int idx = i * 512 + t;
        const int col = idx >> 4, sg = (idx & 15) * 4;
        float4 v = *(const float4*)(g_kP + (size_t)(h * L_ + col) * 64 + sg);
        *(float4*)(smf + SM_KP / 4 + col * KPSTR + sg) = v;
    }
    __syncthreads();   // mbars init + staging visible

    auto issue_chunk = [&](int cc) {
        if (t == 0) {
            const int buf = cc & 1, c = cc & 7;
            const uint32_t mb = sbase + SM_MB + buf * 8;
            const uint32_t d0 = sbase + buf * BUF_SZ;
            const __half* wh = (cc >= 8) ? g_wv_hi : g_wq_hi;
            const __half* wl = (cc >= 8) ? g_wv_lo : g_wq_lo;
            MB_EXPECT_TX(mb, BUF_SZ);
            bulkcp(d0 + OFF_AH, g_walk_hi + (size_t)bt * WBLK + c * WCHK, 10240, mb);
            bulkcp(d0 + OFF_AL, g_walk_lo + (size_t)bt * WBLK + c * WCHK, 10240, mb);
            bulkcp(d0 + OFF_BH, wh + (size_t)h * HBLK + c * HCHK, 20480, mb);
            bulkcp(d0 + OFF_BL, wl + (size_t)h * HBLK + c * HCHK, 20480, mb);
        }
    };

    // ldmatrix lane-address offsets
    uint32_t aoff[2], boff[4];
#pragma unroll
    for (int mt = 0; mt < 2; ++mt)
        aoff[mt] = (uint32_t)(wm * 32 + mt * 16 + (quad & 1) * 8 + lr) * RSTRB + (quad >> 1) * 16;
#pragma unroll
    for (int ng = 0; ng < 4; ++ng)
        boff[ng] = (uint32_t)(wn * 64 + ng * 16 + (quad >> 1) * 8 + lr) * RSTRB + (quad & 1) * 16;

    float acc[2][8][4];
#pragma unroll
    for (int mt = 0; mt < 2; ++mt)
#pragma unroll
        for (int nt = 0; nt < 8; ++nt)
#pragma unroll
            for (int e = 0; e < 4; ++e) acc[mt][nt][e] = 0.f;

    auto compute_chunk = [&](int buf) {
        const uint32_t bbase = sbase + buf * BUF_SZ;
#pragma unroll
        for (int k16 = 0; k16 < 2; ++k16) {
            const uint32_t ko = k16 * 32;
            uint32_t ah[2][4], al[2][4];
#pragma unroll
            for (int mt = 0; mt < 2; ++mt) {
                ldsm4(ah[mt], bbase + OFF_AH + aoff[mt] + ko);
                ldsm4(al[mt], bbase + OFF_AL + aoff[mt] + ko);
            }
#pragma unroll
            for (int ng = 0; ng < 4; ++ng) {
                uint32_t bh[4], bl[4];
                ldsm4(bh, bbase + OFF_BH + boff[ng] + ko);
                ldsm4(bl, bbase + OFF_BL + boff[ng] + ko);
#pragma unroll
                for (int sub = 0; sub < 2; ++sub) {
                    const int nt = ng * 2 + sub;
                    const uint32_t b0 = bh[sub * 2], b1 = bh[sub * 2 + 1];
                    const uint32_t c0 = bl[sub * 2], c1 = bl[sub * 2 + 1];
                    mma16816(acc[0][nt], ah[0], b0, b1);
                    mma16816(acc[1][nt], ah[1], b0, b1);
                    mma16816(acc[0][nt], al[0], b0, b1);
                    mma16816(acc[1][nt], al[1], b0, b1);
                    mma16816(acc[0][nt], ah[0], c0, c1);
                    mma16816(acc[1][nt], ah[1], c0, c1);
                }
            }
        }
    };

    issue_chunk(0);
    issue_chunk(1);
#pragma unroll 1
    for (int cc = 0; cc < 16; ++cc) {
        MB_WAIT(sbase + SM_MB + (cc & 1) * 8, (cc >> 1) & 1);
        compute_chunk(cc & 1);
        __syncthreads();                      // all warps done with this buffer
        if (cc < 14) issue_chunk(cc + 2);     // overwrite is now safe

        if (cc == 7) {
            // ---- q epilogue (overlaps v chunk-0/1 bulk loads) ----
            const float* kp = smf + SM_KP / 4;
            const float* ok = smf + SM_OK / 4;
            const float* ws = smf + SM_WSC / 4;
            float ps[4];
#pragma unroll
            for (int mt = 0; mt < 2; ++mt)
#pragma unroll
                for (int rh = 0; rh < 2; ++rh) {
                    const int row = wm * 32 + mt * 16 + rh * 8 + grp;
                    const int s = row & 63, bloc = row >> 6;
                    float a = 0.f;
#pragma unroll
                    for (int nt = 0; nt < 8; ++nt) {
                        const int col = wn * 64 + nt * 8 + qd * 2;
#pragma unroll
                        for (int cj = 0; cj < 2; ++cj) {
                            const float kv = sigf(ok[bloc * 256 + col + cj] + kp[(col + cj) * KPSTR + s]);
                            const float qv = sigf(acc[mt][nt][rh * 2 + cj]);
                            a += __cosf(qv * kv) * ws[col + cj];
                        }
                    }
                    ps[mt * 2 + rh] = a;
                }
#pragma unroll
            for (int j = 0; j < 4; ++j) {
                ps[j] += __shfl_xor_sync(0xffffffffu, ps[j], 1);
                ps[j] += __shfl_xor_sync(0xffffffffu, ps[j], 2);
            }
            if (qd == 0) {
#pragma unroll
                for (int j = 0; j < 4; ++j) {
                    const int row = wm * 32 + (j >> 1) * 16 + (j & 1) * 8 + grp;
                    smf[SM_SP / 4 + wn * 128 + row] = ps[j];
                }
            }
            __syncthreads();
            if (w < 2) {
                const float* sp = smf + SM_SP / 4;
                const int base = w * 64;
                float v0 = sp[base + l] + sp[128 + base + l] + sp[256 + base + l] + sp[384 + base + l];
                float v1 = sp[base + 32 + l] + sp[128 + base + 32 + l] + sp[256 + base + 32 + l] + sp[384 + base + 32 + l];
                float mx = fmaxf(v0, v1);
#pragma unroll
                for (int o = 16; o; o >>= 1) mx = fmaxf(mx, __shfl_xor_sync(0xffffffffu, mx, o));
                const float e0 = __expf(v0 - mx), e1 = __expf(v1 - mx);
                float sm = e0 + e1;
#pragma unroll
                for (int o = 16; o; o >>= 1) sm += __shfl_xor_sync(0xffffffffu, sm, o);
                smf[SM_WGT / 4 + base + l] = e0;
                smf[SM_WGT / 4 + base + 32 + l] = e1;
                if (l == 0) smf[SM_INV / 4 + w] = __fdividef(1.f, sm);
            }
            __syncthreads();
#pragma unroll
            for (int mt = 0; mt < 2; ++mt)
#pragma unroll
                for (int nt = 0; nt < 8; ++nt)
#pragma unroll
                    for (int e = 0; e < 4; ++e) acc[mt][nt][e] = 0.f;
        }
    }

    // ---- v epilogue: weighted column sums ----
    float w4[4];
#pragma unroll
    for (int j = 0; j < 4; ++j)
        w4[j] = smf[SM_WGT / 4 + wm * 32 + (j >> 1) * 16 + (j & 1) * 8 + grp];
#pragma unroll
    for (int nt = 0; nt < 8; ++nt) {
        float cs0 = 0.f, cs1 = 0.f;
#pragma unroll
        for (int j = 0; j < 4; ++j) {
            cs0 += w4[j] * sigf(acc[j >> 1][nt][(j & 1) * 2 + 0]);
            cs1 += w4[j] * sigf(acc[j >> 1][nt][(j & 1) * 2 + 1]);
        }
#pragma unroll
        for (int o = 4; o <= 16; o <<= 1) {
            cs0 += __shfl_xor_sync(0xffffffffu, cs0, o);
            cs1 += __shfl_xor_sync(0xffffffffu, cs1, o);
        }
        if (grp == 0) {
            const int col = wn * 64 + nt * 8 + qd * 2;
            smf[SM_VP / 4 + wm * 256 + col]     = cs0;
            smf[SM_VP / 4 + wm * 256 + col + 1] = cs1;
        }
    }
    __syncthreads();
    {
        const float* vp = smf + SM_VP / 4;
        const int bloc = t >> 8, col = t & 255;
        const float inv = smf[SM_INV / 4 + bloc];
        const float r = (vp[bloc * 512 + col] + vp[bloc * 512 + 256 + col]) * inv;
        g_res[(size_t)(bt * 2 + bloc) * HL + h * L_ + col] = r;
    }
}

// ---------------- k3: out[:, :256] = sigmoid(res @ O) ----------------
__global__ void __launch_bounds__(256, 2)
k3_out(const float* __restrict__ O, float* __restrict__ out) {
    __shared__ __align__(16) float sA[2][SW * 16];
    __shared__ __align__(16) float sB[2][16 * 64];
    const int ct = blockIdx.x, bt = blockIdx.y;
    const int t = threadIdx.x, tx = t & 15, ty = t >> 4;
    const int ar = t >> 2, ac = (t & 3) * 4;
    const int br = t >> 4, bc = (t & 15) * 4;
    const float* rowBase = g_res + (size_t)bt * 64 * HL;

    unsigned long long acc2[4][2];
#pragma unroll
    for (int i = 0; i < 4; ++i) { acc2[i][0] = 0ull; acc2[i][1] = 0ull; }

    cp16(&sA[0][ar * 16 + ac], rowBase + (size_t)ar * HL + ac);
    cp16(&sB[0][br * 64 + bc], O + (size_t)br * D_ + ct * 64 + bc);
    cp_commit();
#pragma unroll 1
    for (int c = 0; c < 128; ++c) {
        const int cur = c & 1;
        if (c + 1 < 128) {
            const int nb = cur ^ 1;
            cp16(&sA[nb][ar * 16 + ac], rowBase + (size_t)ar * HL + (c + 1) * 16 + ac);
            cp16(&sB[nb][br * 64 + bc], O + (size_t)((c + 1) * 16 + br) * D_ + ct * 64 + bc);
            cp_commit();
            cp_wait<1>();
        } else {
            cp_wait<0>();
        }
        __syncthreads();
#pragma unroll
        for (int k4 = 0; k4 < 4; ++k4) {
            float avv[4][4];
#pragma unroll
            for (int i = 0; i < 4; ++i) {
                float4 tmp = *(const float4*)&sA[cur][(ty * 4 + i) * 16 + k4 * 4];
                avv[i][0] = tmp.x; avv[i][1] = tmp.y; avv[i][2] = tmp.z; avv[i][3] = tmp.w;
            }
#pragma unroll
            for (int q = 0; q < 4; ++q) {
                const int kk = k4 * 4 + q;
                ulonglong2 bb = *(const ulonglong2*)&sB[cur][kk * 64 + tx * 4];
#pragma unroll
                for (int i = 0; i < 4; ++i) {
                    unsigned long long a2 = pack2(avv[i][q], avv[i][q]);
                    acc2[i][0] = fma2(a2, bb.x, acc2[i][0]);
                    acc2[i][1] = fma2(a2, bb.y, acc2[i][1]);
                }
            }
        }
        __syncthreads();
    }
#pragma unroll
    for (int i = 0; i < 4; ++i) {
        const size_t bb = (size_t)bt * 64 + ty * 4 + i;
#pragma unroll
        for (int hf = 0; hf < 2; ++hf) {
            float f0, f1;
            unpack2(acc2[i][hf], f0, f1);
            const int d = ct * 64 + tx * 4 + hf * 2;
            out[bb * 512 + d + 0] = sigf(f0);
            out[bb * 512 + d + 1] = sigf(f1);
        }
    }
}

// ---------------- k4: out[:, 256:512] = origin ----------------
__global__ void k4_copy(const float* __restrict__ x, float* __restrict__ out) {
    const int idx = blockIdx.x * 256 + threadIdx.x;
    const int b = idx >> 6, d4 = (idx & 63) * 4;
    float4 v = *(const float4*)(x + (size_t)b * SD + d4);
    *(float4*)(out + (size_t)b * 512 + 256 + d4) = v;
}

// ---------------- launch ----------------
extern "C" void kernel_launch(void* const* d_in, const int* in_sizes, int n_in,
                              void* d_out, int out_size) {
    const float* x  = (const float*)d_in[0];
    const float* Wq = (const float*)d_in[1];
    const float* Wk = (const float*)d_in[2];
    const float* Wv = (const float*)d_in[3];
    const float* W  = (const float*)d_in[4];
    const float* O  = (const float*)d_in[5];
    const float* P  = (const float*)d_in[6];
    // bias cancels under softmax (constant shift per (b,h)); unused.
    float* out = (float*)d_out;

    cudaFuncSetAttribute(k2_mma, cudaFuncAttributeMaxDynamicSharedMemorySize, SMEM_K2);

    p_walk<<<WROWS * 64 / 256, 256>>>(x);
    p_wt<<<dim3(H_ * L_ * D_ / 256, 2), 256>>>(Wq, Wv);
    k1_preK<<<dim3(H_, 33), 256>>>(x, Wk, P);
    k1t<<<HL * SW / 256, 256>>>();
    k2_mma<<<dim3(H_, B_ / 2), 512, SMEM_K2>>>(W);
    k3_out<<<dim3(4, 32), 256>>>(O, out);
    k4_copy<<<512, 256>>>(x, out);
}

// round 15
// speedup vs baseline: 2.4996x; 1.0023x over previous
#include <cuda_runtime.h>
#include <cuda_fp16.h>
#include <cstdint>
#include <cstddef>

#define B_  2048
#define S_  65
#define SW  64
#define D_  256
#define H_  8
#define L_  256
#define HL  2048
#define SD  (S_*D_)        // 16640
#define WROWS (B_*SW)      // 131072

// chunk-blocked layouts (halves): walk: [bt][c][128 rows][40], weights: [h][c][256 rows][40]
#define WBLK  40960        // per-bt block (8 chunks * 128 * 40)
#define WCHK  5120         // per-chunk (128*40)
#define HBLK  81920        // per-h block (8 chunks * 256 * 40)
#define HCHK  10240        // per-chunk (256*40)

// ---------------- device scratch ----------------
__device__ __align__(16) float  g_A[(B_ + SW) * HL];   // preK raw preacts
__device__ __align__(16) float  g_kP[HL * SW];         // P-part transposed: [h*L+l][s]
__device__ __align__(16) float  g_res[B_ * HL];
__device__ __align__(16) __half g_walk_hi[1024 * WBLK];
__device__ __align__(16) __half g_walk_lo[1024 * WBLK];
__device__ __align__(16) __half g_wq_hi[H_ * HBLK];
__device__ __align__(16) __half g_wq_lo[H_ * HBLK];
__device__ __align__(16) __half g_wv_hi[H_ * HBLK];
__device__ __align__(16) __half g_wv_lo[H_ * HBLK];

// ---------------- helpers ----------------
__device__ __forceinline__ float sigf(float x) {
    return __fdividef(1.0f, 1.0f + __expf(-x));
}
__device__ __forceinline__ unsigned long long pack2(float x, float y) {
    unsigned long long r;
    asm("mov.b64 %0, {%1, %2};" : "=l"(r) : "f"(x), "f"(y));
    return r;
}
__device__ __forceinline__ void unpack2(unsigned long long v, float& x, float& y) {
    asm("mov.b64 {%0, %1}, %2;" : "=f"(x), "=f"(y) : "l"(v));
}
__device__ __forceinline__ unsigned long long fma2(unsigned long long a, unsigned long long b,
                                                   unsigned long long c) {
    unsigned long long d;
    asm("fma.rn.f32x2 %0, %1, %2, %3;" : "=l"(d) : "l"(a), "l"(b), "l"(c));
    return d;
}
__device__ __forceinline__ void cp16(void* s, const void* g) {
    unsigned sa = (unsigned)__cvta_generic_to_shared(s);
    asm volatile("cp.async.cg.shared.global [%0], [%1], 16;\n" ::"r"(sa), "l"(g));
}
__device__ __forceinline__ void cp_commit() { asm volatile("cp.async.commit_group;\n"); }
template <int N>
__device__ __forceinline__ void cp_wait() { asm volatile("cp.async.wait_group %0;\n" ::"n"(N)); }

__device__ __forceinline__ uint32_t smem_u32(const void* p) {
    uint32_t a;
    asm("{ .reg .u64 t0; cvta.to.shared.u64 t0, %1; cvt.u32.u64 %0, t0; }" : "=r"(a) : "l"(p));
    return a;
}

// m16n8k16 fp16 -> fp32 mma
__device__ __forceinline__ void mma16816(float* c, const uint32_t* a, uint32_t b0, uint32_t b1) {
    asm volatile("mma.sync.aligned.m16n8k16.row.col.f32.f16.f16.f32 "
        "{%0,%1,%2,%3}, {%4,%5,%6,%7}, {%8,%9}, {%0,%1,%2,%3};"
        : "+f"(c[0]), "+f"(c[1]), "+f"(c[2]), "+f"(c[3])
        : "r"(a[0]), "r"(a[1]), "r"(a[2]), "r"(a[3]), "r"(b0), "r"(b1));
}
__device__ __forceinline__ void ldsm4(uint32_t* r, uint32_t addr) {
    asm volatile("ldmatrix.sync.aligned.m8n8.x4.shared.b16 {%0,%1,%2,%3}, [%4];"
        : "=r"(r[0]), "=r"(r[1]), "=r"(r[2]), "=r"(r[3]) : "r"(addr));
}

// bulk async copy global -> shared, mbarrier completion (sm_90)
__device__ __forceinline__ void bulkcp(uint32_t dst, const void* src, uint32_t bytes, uint32_t mbar) {
    asm volatile("cp.async.bulk.shared::cluster.global.mbarrier::complete_tx::bytes [%0], [%1], %2, [%3];"
        :: "r"(dst), "l"(src), "r"(bytes), "r"(mbar) : "memory");
}
#define MB_INIT(mb, c)  asm volatile("mbarrier.init.shared.b64 [%0], %1;" :: "r"((uint32_t)(mb)), "r"((uint32_t)(c)) : "memory")
#define MB_EXPECT_TX(mb, n) asm volatile("mbarrier.arrive.expect_tx.shared.b64 _, [%0], %1;" :: "r"((uint32_t)(mb)), "r"((uint32_t)(n)) : "memory")
#define MB_WAIT(mb, par) do { \
    uint32_t _m = (uint32_t)(mb), _p = (uint32_t)(par), _d; \
    asm volatile("{\n\t.reg .pred p;\n\t" \
        "mbarrier.try_wait.parity.acquire.cta.shared::cta.b64 p, [%1], %2;\n\t" \
        "selp.b32 %0, 1, 0, p;\n\t}" : "=r"(_d) : "r"(_m), "r"(_p) : "memory"); \
    if (!_d) { \
        asm volatile("{\n\t.reg .pred P1;\n\t" \
            "WL_%=:\n\t" \
            "mbarrier.try_wait.parity.acquire.cta.shared::cta.b64 P1, [%0], %1, 0x989680;\n\t" \
            "@P1 bra.uni WD_%=;\n\t" \
            "bra.uni WL_%=;\n\t" \
            "WD_%=:\n\t}" :: "r"(_m), "r"(_p) : "memory"); \
    } \
} while (0)

// ---------------- k2 smem layout (bytes) ----------------
#define RSTRB 80
#define OFF_AH 0
#define OFF_AL 10240
#define OFF_BH 20480
#define OFF_BL 40960
#define BUF_SZ 61440
#define SM_MB  122880
#define KPSTR  68
#define SM_KP  122912
#define SM_OK  192544
#define SM_WSC 194592
#define SM_SP  195616
#define SM_WGT 197664
#define SM_VP  198176
#define SM_INV 202272
#define SMEM_K2 202288

// ---------------- prep: split walk rows into fp16 hi/lo (chunk-blocked) ----------------
__global__ void p_walk(const float* __restrict__ x) {
    const int idx = blockIdx.x * 256 + threadIdx.x;
    const int row = idx >> 6, d = (idx & 63) * 4;
    const int b = row >> 6, s = row & 63;
    float4 v = *(const float4*)(x + (size_t)b * SD + (size_t)(s + 1) * D_ + d);
    __half h0 = __float2half_rn(v.x), h1 = __float2half_rn(v.y);
    __half h2 = __float2half_rn(v.z), h3 = __float2half_rn(v.w);
    const int bt = row >> 7, tr = row & 127;
    const size_t o = (size_t)bt * WBLK + (d >> 5) * WCHK + tr * 40 + (d & 31);
    *(__half2*)(g_walk_hi + o)     = __halves2half2(h0, h1);
    *(__half2*)(g_walk_hi + o + 2) = __halves2half2(h2, h3);
    *(__half2*)(g_walk_lo + o)     = __halves2half2(__float2half_rn(v.x - __half2float(h0)),
                                                    __float2half_rn(v.y - __half2float(h1)));
    *(__half2*)(g_walk_lo + o + 2) = __halves2half2(__float2half_rn(v.z - __half2float(h2)),
                                                    __float2half_rn(v.w - __half2float(h3)));
}

// ---------------- prep: transpose + split weights (h,d,l) -> chunk-blocked [h][c][l][40] ----------------
__global__ void p_wt(const float* __restrict__ Wq, const float* __restrict__ Wv) {
    const int idx = blockIdx.x * 256 + threadIdx.x;
    const int h = idx >> 16, l = (idx >> 8) & 255, d = idx & 255;
    const float* src = (blockIdx.y == 0) ? Wq : Wv;
    float v = src[(size_t)h * 65536 + (size_t)d * 256 + l];
    __half hi = __float2half_rn(v);
    __half lo = __float2half_rn(v - __half2float(hi));
    const size_t o = (size_t)h * HBLK + (d >> 5) * HCHK + l * 40 + (d & 31);
    if (blockIdx.y == 0) { g_wq_hi[o] = hi; g_wq_lo[o] = lo; }
    else                 { g_wv_hi[o] = hi; g_wv_lo[o] = lo; }
}

// ---------------- k1t: transpose P-part of preK into [hl][s] ----------------
__global__ void k1t(void) {
    const int idx = blockIdx.x * 256 + threadIdx.x;
    const int hl = idx >> 6, s = idx & 63;
    g_kP[idx] = g_A[(size_t)(B_ + s) * HL + hl];
}

// ---------------- fp32 GEMM core (k1, k3) ----------------
template <int NCH>
__device__ __forceinline__ void gemm64x256(const float* __restrict__ rowBase, int rowStride,
                                           const float* __restrict__ Wg,
                                           unsigned long long (&acc2)[4][8],
                                           float (&sA)[2][SW * 16], float (&sB)[2][16 * L_],
                                           int t, int tx, int ty) {
    const int ar = t >> 2, ac = (t & 3) * 4;
    const int br = t >> 4, bc = (t & 15) * 16;
    {
        cp16(&sA[0][ar * 16 + ac], rowBase + (size_t)ar * rowStride + ac);
        const float* src = Wg + (size_t)br * L_ + bc;
        float* dst = &sB[0][br * L_ + bc];
        cp16(dst + 0, src + 0); cp16(dst + 4, src + 4);
        cp16(dst + 8, src + 8); cp16(dst + 12, src + 12);
        cp_commit();
    }
#pragma unroll 1
    for (int c = 0; c < NCH; ++c) {
        const int cur = c & 1;
        if (c + 1 < NCH) {
            const int nb = cur ^ 1;
            cp16(&sA[nb][ar * 16 + ac], rowBase + (size_t)ar * rowStride + (c + 1) * 16 + ac);
            const float* src = Wg + (size_t)((c + 1) * 16 + br) * L_ + bc;
            float* dst = &sB[nb][br * L_ + bc];
            cp16(dst + 0, src + 0); cp16(dst + 4, src + 4);
            cp16(dst + 8, src + 8); cp16(dst + 12, src + 12);
            cp_commit();
            cp_wait<1>();
        } else {
            cp_wait<0>();
        }
        __syncthreads();
#pragma unroll
        for (int k4 = 0; k4 < 4; ++k4) {
            float avv[4][4];
#pragma unroll
            for (int i = 0; i < 4; ++i) {
                float4 tmp = *(const float4*)&sA[cur][(ty * 4 + i) * 16 + k4 * 4];
                avv[i][0] = tmp.x; avv[i][1] = tmp.y; avv[i][2] = tmp.z; avv[i][3] = tmp.w;
            }
#pragma unroll
            for (int q = 0; q < 4; ++q) {
                unsigned long long a2[4];
#pragma unroll
                for (int i = 0; i < 4; ++i) a2[i] = pack2(avv[i][q], avv[i][q]);
                const int kk = k4 * 4 + q;
#pragma unroll
                for (int g = 0; g < 4; ++g) {
                    ulonglong2 bb = *(const ulonglong2*)&sB[cur][kk * L_ + tx * 4 + g * 64];
#pragma unroll
                    for (int i = 0; i < 4; ++i) {
                        acc2[i][g * 2 + 0] = fma2(a2[i], bb.x, acc2[i][g * 2 + 0]);
                        acc2[i][g * 2 + 1] = fma2(a2[i], bb.y, acc2[i][g * 2 + 1]);
                    }
                }
            }
        }
        __syncthreads();
    }
}

// ---------------- k1: preK = [origin ; P] @ Wk ----------------
__global__ void __launch_bounds__(256, 2)
k1_preK(const float* __restrict__ x, const float* __restrict__ Wk, const float* __restrict__ P) {
    __shared__ __align__(16) float sA[2][SW * 16];
    __shared__ __align__(16) float sB[2][16 * L_];
    const int h = blockIdx.x, mt = blockIdx.y;
    const int t = threadIdx.x, tx = t & 15, ty = t >> 4;
    const float* base; int stride;
    if (mt < 32) { base = x + (size_t)mt * 64 * SD; stride = SD; }
    else         { base = P; stride = D_; }
    unsigned long long acc2[4][8];
#pragma unroll
    for (int i = 0; i < 4; ++i)
#pragma unroll
        for (int p = 0; p < 8; ++p) acc2[i][p] = 0ull;
    gemm64x256<16>(base, stride, Wk + h * (D_ * L_), acc2, sA, sB, t, tx, ty);
#pragma unroll
    for (int i = 0; i < 4; ++i) {
        const size_t row = (size_t)mt * 64 + ty * 4 + i;
        float* dst = g_A + row * HL + h * L_ + tx * 4;
#pragma unroll
        for (int g = 0; g < 4; ++g)
#pragma unroll
            for (int hf = 0; hf < 2; ++hf) {
                float f0, f1;
                unpack2(acc2[i][g * 2 + hf], f0, f1);
                dst[g * 64 + hf * 2 + 0] = f0;
                dst[g * 64 + hf * 2 + 1] = f1;
            }
    }
}

// ---------------- k2: HMMA fused q/score/softmax/v (bulk-copy pipeline) ----------------
__global__ void __launch_bounds__(512, 1)
k2_mma(const float* __restrict__ Wsc) {
    extern __shared__ char smem[];
    float* smf = (float*)smem;
    const uint32_t sbase = smem_u32(smem);
    const int h = blockIdx.x, bt = blockIdx.y;
    const int t = threadIdx.x, w = t >> 5, l = t & 31;
    const int wm = w & 3, wn = w >> 2;
    const int grp = l >> 2, qd = l & 3;
    const int lr = l & 7, quad = l >> 3;

    if (t == 0) { MB_INIT(sbase + SM_MB, 1); MB_INIT(sbase + SM_MB + 8, 1); }

    // ---- stage ok / wsc / kp ----
    smf[SM_OK / 4 + t] = g_A[(size_t)(bt * 2 + (t >> 8)) * HL + h * L_ + (t & 255)];
    if (t < 256) smf[SM_WSC / 4 + t] = Wsc[h * L_ + t];
#pragma unroll
    for (int i = 0; i < 8; ++i) {
        const int idx = i * 512 + t;
        const int col = idx >> 4, sg = (idx & 15) * 4;
        float4 v = *(const float4*)(g_kP + (size_t)(h * L_ + col) * 64 + sg);
        *(float4*)(smf + SM_KP / 4 + col * KPSTR + sg) = v;
    }
    __syncthreads();   // mbars init + staging visible

    auto issue_chunk = [&](int cc) {
        if (t == 0) {
            const int buf = cc & 1, c = cc & 7;
            const uint32_t mb = sbase + SM_MB + buf * 8;
            const uint32_t d0 = sbase + buf * BUF_SZ;
            const __half* wh = (cc >= 8) ? g_wv_hi : g_wq_hi;
            const __half* wl = (cc >= 8) ? g_wv_lo : g_wq_lo;
            MB_EXPECT_TX(mb, BUF_SZ);
            bulkcp(d0 + OFF_AH, g_walk_hi + (size_t)bt * WBLK + c * WCHK, 10240, mb);
            bulkcp(d0 + OFF_AL, g_walk_lo + (size_t)bt * WBLK + c * WCHK, 10240, mb);
            bulkcp(d0 + OFF_BH, wh + (size_t)h * HBLK + c * HCHK, 20480, mb);
            bulkcp(d0 + OFF_BL, wl + (size_t)h * HBLK + c * HCHK, 20480, mb);
        }
    };

    // ldmatrix lane-address offsets
    uint32_t aoff[2], boff[4];
#pragma unroll
    for (int mt = 0; mt < 2; ++mt)
        aoff[mt] = (uint32_t)(wm * 32 + mt * 16 + (quad & 1) * 8 + lr) * RSTRB + (quad >> 1) * 16;
#pragma unroll
    for (int ng = 0; ng < 4; ++ng)
        boff[ng] = (uint32_t)(wn * 64 + ng * 16 + (quad >> 1) * 8 + lr) * RSTRB + (quad & 1) * 16;

    float acc[2][8][4];
#pragma unroll
    for (int mt = 0; mt < 2; ++mt)
#pragma unroll
        for (int nt = 0; nt < 8; ++nt)
#pragma unroll
            for (int e = 0; e < 4; ++e) acc[mt][nt][e] = 0.f;

    auto compute_chunk = [&](int buf) {
        const uint32_t bbase = sbase + buf * BUF_SZ;
#pragma unroll
        for (int k16 = 0; k16 < 2; ++k16) {
            const uint32_t ko = k16 * 32;
            uint32_t ah[2][4], al[2][4];
#pragma unroll
            for (int mt = 0; mt < 2; ++mt) {
                ldsm4(ah[mt], bbase + OFF_AH + aoff[mt] + ko);
                ldsm4(al[mt], bbase + OFF_AL + aoff[mt] + ko);
            }
#pragma unroll
            for (int ng = 0; ng < 4; ++ng) {
                uint32_t bh[4], bl[4];
                ldsm4(bh, bbase + OFF_BH + boff[ng] + ko);
                ldsm4(bl, bbase + OFF_BL + boff[ng] + ko);
#pragma unroll
                for (int sub = 0; sub < 2; ++sub) {
                    const int nt = ng * 2 + sub;
                    const uint32_t b0 = bh[sub * 2], b1 = bh[sub * 2 + 1];
                    const uint32_t c0 = bl[sub * 2], c1 = bl[sub * 2 + 1];
                    mma16816(acc[0][nt], ah[0], b0, b1);
                    mma16816(acc[1][nt], ah[1], b0, b1);
                    mma16816(acc[0][nt], al[0], b0, b1);
                    mma16816(acc[1][nt], al[1], b0, b1);
                    mma16816(acc[0][nt], ah[0], c0, c1);
                    mma16816(acc[1][nt], ah[1], c0, c1);
                }
            }
        }
    };

    issue_chunk(0);
    issue_chunk(1);
#pragma unroll 1
    for (int cc = 0; cc < 16; ++cc) {
        MB_WAIT(sbase + SM_MB + (cc & 1) * 8, (cc >> 1) & 1);
        compute_chunk(cc & 1);
        __syncthreads();                      // all warps done with this buffer
        if (cc < 14) issue_chunk(cc + 2);     // overwrite is now safe

        if (cc == 7) {
            // ---- q epilogue (overlaps v chunk-0/1 bulk loads) ----
            const float* kp = smf + SM_KP / 4;
            const float* ok = smf + SM_OK / 4;
            const float* ws = smf + SM_WSC / 4;
            float ps[4];
#pragma unroll
            for (int mt = 0; mt < 2; ++mt)
#pragma unroll
                for (int rh = 0; rh < 2; ++rh) {
                    const int row = wm * 32 + mt * 16 + rh * 8 + grp;
                    const int s = row & 63, bloc = row >> 6;
                    float a = 0.f;
#pragma unroll
                    for (int nt = 0; nt < 8; ++nt) {
                        const int col = wn * 64 + nt * 8 + qd * 2;
#pragma unroll
                        for (int cj = 0; cj < 2; ++cj) {
                            const float kv = sigf(ok[bloc * 256 + col + cj] + kp[(col + cj) * KPSTR + s]);
                            const float qv = sigf(acc[mt][nt][rh * 2 + cj]);
                            a += __cosf(qv * kv) * ws[col + cj];
                        }
                    }
                    ps[mt * 2 + rh] = a;
                }
#pragma unroll
            for (int j = 0; j < 4; ++j) {
                ps[j] += __shfl_xor_sync(0xffffffffu, ps[j], 1);
                ps[j] += __shfl_xor_sync(0xffffffffu, ps[j], 2);
            }
            if (qd == 0) {
#pragma unroll
                for (int j = 0; j < 4; ++j) {
                    const int row = wm * 32 + (j >> 1) * 16 + (j & 1) * 8 + grp;
                    smf[SM_SP / 4 + wn * 128 + row] = ps[j];
                }
            }
            __syncthreads();
            if (w < 2) {
                const float* sp = smf + SM_SP / 4;
                const int base = w * 64;
                float v0 = sp[base + l] + sp[128 + base + l] + sp[256 + base + l] + sp[384 + base + l];
                float v1 = sp[base + 32 + l] + sp[128 + base + 32 + l] + sp[256 + base + 32 + l] + sp[384 + base + 32 + l];
                float mx = fmaxf(v0, v1);
#pragma unroll
                for (int o = 16; o; o >>= 1) mx = fmaxf(mx, __shfl_xor_sync(0xffffffffu, mx, o));
                const float e0 = __expf(v0 - mx), e1 = __expf(v1 - mx);
                float sm = e0 + e1;
#pragma unroll
                for (int o = 16; o; o >>= 1) sm += __shfl_xor_sync(0xffffffffu, sm, o);
                smf[SM_WGT / 4 + base + l] = e0;
                smf[SM_WGT / 4 + base + 32 + l] = e1;
                if (l == 0) smf[SM_INV / 4 + w] = __fdividef(1.f, sm);
            }
            __syncthreads();
#pragma unroll
            for (int mt = 0; mt < 2; ++mt)
#pragma unroll
                for (int nt = 0; nt < 8; ++nt)
#pragma unroll
                    for (int e = 0; e < 4; ++e) acc[mt][nt][e] = 0.f;
        }
    }

    // ---- v epilogue: weighted column sums ----
    float w4[4];
#pragma unroll
    for (int j = 0; j < 4; ++j)
        w4[j] = smf[SM_WGT / 4 + wm * 32 + (j >> 1) * 16 + (j & 1) * 8 + grp];
#pragma unroll
    for (int nt = 0; nt < 8; ++nt) {
        float cs0 = 0.f, cs1 = 0.f;
#pragma unroll
        for (int j = 0; j < 4; ++j) {
            cs0 += w4[j] * sigf(acc[j >> 1][nt][(j & 1) * 2 + 0]);
            cs1 += w4[j] * sigf(acc[j >> 1][nt][(j & 1) * 2 + 1]);
        }
#pragma unroll
        for (int o = 4; o <= 16; o <<= 1) {
            cs0 += __shfl_xor_sync(0xffffffffu, cs0, o);
            cs1 += __shfl_xor_sync(0xffffffffu, cs1, o);
        }
        if (grp == 0) {
            const int col = wn * 64 + nt * 8 + qd * 2;
            smf[SM_VP / 4 + wm * 256 + col]     = cs0;
            smf[SM_VP / 4 + wm * 256 + col + 1] = cs1;
        }
    }
    __syncthreads();
    {
        const float* vp = smf + SM_VP / 4;
        const int bloc = t >> 8, col = t & 255;
        const float inv = smf[SM_INV / 4 + bloc];
        const float r = (vp[bloc * 512 + col] + vp[bloc * 512 + 256 + col]) * inv;
        g_res[(size_t)(bt * 2 + bloc) * HL + h * L_ + col] = r;
    }
}

// ---------------- k3: out[:, :256] = sigmoid(res @ O) ----------------
__global__ void __launch_bounds__(256, 2)
k3_out(const float* __restrict__ O, float* __restrict__ out) {
    __shared__ __align__(16) float sA[2][SW * 16];
    __shared__ __align__(16) float sB[2][16 * 64];
    const int ct = blockIdx.x, bt = blockIdx.y;
    const int t = threadIdx.x, tx = t & 15, ty = t >> 4;
    const int ar = t >> 2, ac = (t & 3) * 4;
    const int br = t >> 4, bc = (t & 15) * 4;
    const float* rowBase = g_res + (size_t)bt * 64 * HL;

    unsigned long long acc2[4][2];
#pragma unroll
    for (int i = 0; i < 4; ++i) { acc2[i][0] = 0ull; acc2[i][1] = 0ull; }

    cp16(&sA[0][ar * 16 + ac], rowBase + (size_t)ar * HL + ac);
    cp16(&sB[0][br * 64 + bc], O + (size_t)br * D_ + ct * 64 + bc);
    cp_commit();
#pragma unroll 1
    for (int c = 0; c < 128; ++c) {
        const int cur = c & 1;
        if (c + 1 < 128) {
            const int nb = cur ^ 1;
            cp16(&sA[nb][ar * 16 + ac], rowBase + (size_t)ar * HL + (c + 1) * 16 + ac);
            cp16(&sB[nb][br * 64 + bc], O + (size_t)((c + 1) * 16 + br) * D_ + ct * 64 + bc);
            cp_commit();
            cp_wait<1>();
        } else {
            cp_wait<0>();
        }
        __syncthreads();
#pragma unroll
        for (int k4 = 0; k4 < 4; ++k4) {
            float avv[4][4];
#pragma unroll
            for (int i = 0; i < 4; ++i) {
                float4 tmp = *(const float4*)&sA[cur][(ty * 4 + i) * 16 + k4 * 4];
                avv[i][0] = tmp.x; avv[i][1] = tmp.y; avv[i][2] = tmp.z; avv[i][3] = tmp.w;
            }
#pragma unroll
            for (int q = 0; q < 4; ++q) {
                const int kk = k4 * 4 + q;
                ulonglong2 bb = *(const ulonglong2*)&sB[cur][kk * 64 + tx * 4];
#pragma unroll
                for (int i = 0; i < 4; ++i) {
                    unsigned long long a2 = pack2(avv[i][q], avv[i][q]);
                    acc2[i][0] = fma2(a2, bb.x, acc2[i][0]);
                    acc2[i][1] = fma2(a2, bb.y, acc2[i][1]);
                }
            }
        }
        __syncthreads();
    }
#pragma unroll
    for (int i = 0; i < 4; ++i) {
        const size_t bb = (size_t)bt * 64 + ty * 4 + i;
#pragma unroll
        for (int hf = 0; hf < 2; ++hf) {
            float f0, f1;
            unpack2(acc2[i][hf], f0, f1);
            const int d = ct * 64 + tx * 4 + hf * 2;
            out[bb * 512 + d + 0] = sigf(f0);
            out[bb * 512 + d + 1] = sigf(f1);
        }
    }
}

// ---------------- k4: out[:, 256:512] = origin ----------------
__global__ void k4_copy(const float* __restrict__ x, float* __restrict__ out) {
    const int idx = blockIdx.x * 256 + threadIdx.x;
    const int b = idx >> 6, d4 = (idx & 63) * 4;
    float4 v = *(const float4*)(x + (size_t)b * SD + d4);
    *(float4*)(out + (size_t)b * 512 + 256 + d4) = v;
}

// ---------------- launch ----------------
extern "C" void kernel_launch(void* const* d_in, const int* in_sizes, int n_in,
                              void* d_out, int out_size) {
    const float* x  = (const float*)d_in[0];
    const float* Wq = (const float*)d_in[1];
    const float* Wk = (const float*)d_in[2];
    const float* Wv = (const float*)d_in[3];
    const float* W  = (const float*)d_in[4];
    const float* O  = (const float*)d_in[5];
    const float* P  = (const float*)d_in[6];
    // bias cancels under softmax (constant shift per (b,h)); unused.
    float* out = (float*)d_out;

    cudaFuncSetAttribute(k2_mma, cudaFuncAttributeMaxDynamicSharedMemorySize, SMEM_K2);

    p_walk<<<WROWS * 64 / 256, 256>>>(x);
    p_wt<<<dim3(H_ * L_ * D_ / 256, 2), 256>>>(Wq, Wv);
    k1_preK<<<dim3(H_, 33), 256>>>(x, Wk, P);
    k1t<<<HL * SW / 256, 256>>>();
    k2_mma<<<dim3(H_, B_ / 2), 512, SMEM_K2>>>(W);
    k3_out<<<dim3(4, 32), 256>>>(O, out);
    k4_copy<<<512, 256>>>(x, out);
}